// round 6
// baseline (speedup 1.0000x reference)
#include <cuda_runtime.h>
#include <cuda_bf16.h>
#include <math.h>
#include <stdint.h>

// Problem constants
#define N_NODES   100000
#define N_EDGES   600000
#define N_GRAPHS  1000
#define VOCAB     10000
#define D         128
#define TM        128              // rows per tile
#define ROWB      272              // padded smem row stride in bytes (136 bf16)
#define TILE_B    (128 * ROWB)     // 34816 bytes per 128x128 bf16 tile

// ---------------- scratch -------------------------------------------------
__device__ float g_x[N_NODES * D];      // buffer A
__device__ float g_y[N_NODES * D];      // buffer B
__device__ float g_embT[VOCAB * D];
__device__ float g_pool[N_GRAPHS * D];
__device__ int   g_cnt[N_NODES];        // degree histogram
__device__ int   g_cur[N_NODES];        // fill cursors (copy of rowptr)
__device__ int   g_rowptr[N_NODES + 1];
__device__ int   g_adj[N_EDGES];        // src node ids grouped by dst
// split-bf16 weights, transposed [n][k]; mats 0..2 = conv_w1[L], 3..5 = conv_w2[L]
__device__ __nv_bfloat16 g_wh[6][D * D];
__device__ __nv_bfloat16 g_wl[6][D * D];

// ---------------- helpers -------------------------------------------------
__device__ __forceinline__ uint32_t smem_u32(const void* p) {
    uint32_t a;
    asm("{ .reg .u64 t; cvta.to.shared.u64 t, %1; cvt.u32.u64 %0, t; }"
        : "=r"(a) : "l"(p));
    return a;
}

__device__ __forceinline__ uint32_t pack_bf16(float a, float b) {
    __nv_bfloat162 t;
    t.x = __float2bfloat16_rn(a);
    t.y = __float2bfloat16_rn(b);
    return *(uint32_t*)&t;
}

__device__ __forceinline__ void mma16816(float* d, uint32_t a0, uint32_t a1,
                                         uint32_t a2, uint32_t a3,
                                         uint32_t b0, uint32_t b1) {
    asm volatile(
        "mma.sync.aligned.m16n8k16.row.col.f32.bf16.bf16.f32 "
        "{%0,%1,%2,%3}, {%4,%5,%6,%7}, {%8,%9}, {%0,%1,%2,%3};\n"
        : "+f"(d[0]), "+f"(d[1]), "+f"(d[2]), "+f"(d[3])
        : "r"(a0), "r"(a1), "r"(a2), "r"(a3), "r"(b0), "r"(b1));
}

__device__ __forceinline__ void ldm_x4(uint32_t& r0, uint32_t& r1, uint32_t& r2,
                                       uint32_t& r3, uint32_t addr) {
    asm volatile("ldmatrix.sync.aligned.m8n8.x4.shared.b16 {%0,%1,%2,%3}, [%4];"
                 : "=r"(r0), "=r"(r1), "=r"(r2), "=r"(r3) : "r"(addr));
}

__device__ __forceinline__ void ldm_x2(uint32_t& r0, uint32_t& r1, uint32_t addr) {
    asm volatile("ldmatrix.sync.aligned.m8n8.x2.shared.b16 {%0,%1}, [%2];"
                 : "=r"(r0), "=r"(r1) : "r"(addr));
}

// ---------------- CSR build -------------------------------------------------
__global__ void zero_kernel() {
    int i = blockIdx.x * blockDim.x + threadIdx.x;
    int n = gridDim.x * blockDim.x;
    for (int j = i; j < N_NODES; j += n) g_cnt[j] = 0;
    for (int j = i; j < N_GRAPHS * D; j += n) g_pool[j] = 0.0f;
}

__global__ void hist_kernel(const int* __restrict__ dst, int nE) {
    int i = blockIdx.x * blockDim.x + threadIdx.x;
    if (i < nE) atomicAdd(&g_cnt[dst[i]], 1);
}

__global__ void __launch_bounds__(1024, 1) scan_kernel(int nNodes) {
    __shared__ int part[1024];
    const int tid = threadIdx.x;
    const int P = (nNodes + 1023) / 1024;
    const int base = tid * P;
    int s = 0;
    for (int i = 0; i < P; ++i) {
        int k = base + i;
        if (k < nNodes) s += g_cnt[k];
    }
    part[tid] = s;
    __syncthreads();
    int v = part[tid];
    for (int off = 1; off < 1024; off <<= 1) {
        int t = (tid >= off) ? part[tid - off] : 0;
        __syncthreads();
        part[tid] += t;
        __syncthreads();
    }
    int excl = part[tid] - v;
    int run = excl;
    for (int i = 0; i < P; ++i) {
        int k = base + i;
        if (k < nNodes) { g_rowptr[k] = run; g_cur[k] = run; run += g_cnt[k]; }
    }
    if (tid == 1023) g_rowptr[nNodes] = run;
}

__global__ void fill_kernel(const int* __restrict__ src,
                            const int* __restrict__ dst, int nE) {
    int i = blockIdx.x * blockDim.x + threadIdx.x;
    if (i >= nE) return;
    int pos = atomicAdd(&g_cur[dst[i]], 1);
    g_adj[pos] = src[i];
}

// ---------------- weight prep -----------------------------------------------
__global__ void prep_weights(const float* __restrict__ w1,
                             const float* __restrict__ w2) {
    int i = blockIdx.x * blockDim.x + threadIdx.x;
    if (i >= 6 * D * D) return;
    int m = i / (D * D), kn = i % (D * D);
    int k = kn / D, n = kn % D;
    float v = (m < 3) ? w1[m * D * D + kn] : w2[(m - 3) * D * D + kn];
    __nv_bfloat16 h = __float2bfloat16_rn(v);
    __nv_bfloat16 l = __float2bfloat16_rn(v - __bfloat162float(h));
    g_wh[m][n * D + k] = h;
    g_wl[m][n * D + k] = l;
}

// ---------------- GEMM phase ------------------------------------------------
__device__ __forceinline__ void gemm_phase(uint32_t aH, uint32_t aL,
                                           uint32_t bH, uint32_t bL,
                                           float (&acc)[4][4][4]) {
#pragma unroll
    for (int k0 = 0; k0 < D; k0 += 16) {
        uint32_t ah0[4], ah1[4], ah2[4], ah3[4];
        uint32_t al0[4], al1[4], al2[4], al3[4];
        uint32_t bh0[4], bh1[4], bl0[4], bl1[4];
#pragma unroll
        for (int mt = 0; mt < 4; ++mt) {
            ldm_x4(ah0[mt], ah1[mt], ah2[mt], ah3[mt], aH + mt * (16 * ROWB) + k0 * 2);
            ldm_x4(al0[mt], al1[mt], al2[mt], al3[mt], aL + mt * (16 * ROWB) + k0 * 2);
        }
#pragma unroll
        for (int nt = 0; nt < 4; ++nt) {
            ldm_x2(bh0[nt], bh1[nt], bH + nt * (8 * ROWB) + k0 * 2);
            ldm_x2(bl0[nt], bl1[nt], bL + nt * (8 * ROWB) + k0 * 2);
        }
#pragma unroll
        for (int mt = 0; mt < 4; ++mt) {
#pragma unroll
            for (int nt = 0; nt < 4; ++nt) {
                mma16816(acc[mt][nt], ah0[mt], ah1[mt], ah2[mt], ah3[mt], bh0[nt], bh1[nt]);
                mma16816(acc[mt][nt], ah0[mt], ah1[mt], ah2[mt], ah3[mt], bl0[nt], bl1[nt]);
                mma16816(acc[mt][nt], al0[mt], al1[mt], al2[mt], al3[mt], bh0[nt], bh1[nt]);
            }
        }
    }
}

// ---------------- persistent fused aggregate+MLP ----------------------------
// MODE 0: out = x @ W[w2_id]                      (plain rows, no agg)
// MODE 1: A = sum embT[x_idx[self+nbrs]]; h = relu(A + b1); out = relu(h@W2 + b2)
// MODE 2: A = x[self] + sum x[nbrs]; h = relu(A@W1 + b1); out = relu(h@W2 + b2)
// pbatch != nullptr: no out write; red.add result into g_pool[batch[row]].
template <int MODE>
__global__ void __launch_bounds__(256, 1)
mlp_mma(const float* __restrict__ x, const int* __restrict__ xidx,
        int w1_id, int w2_id,
        const float* __restrict__ b1, const float* __restrict__ b2,
        float* __restrict__ out, const int* __restrict__ pbatch,
        int nRows, int nTiles) {
    extern __shared__ __align__(16) unsigned char sm[];
    unsigned char* Ah  = sm;
    unsigned char* Al  = sm + TILE_B;
    unsigned char* W2h = sm + 2 * TILE_B;
    unsigned char* W2l = sm + 3 * TILE_B;
    unsigned char* W1h = sm + 4 * TILE_B;   // MODE 2 only
    unsigned char* W1l = sm + 5 * TILE_B;
    __shared__ float b1s[D], b2s[D];

    const int tid  = threadIdx.x;
    const int lane = tid & 31, wid = tid >> 5;
    const int R0 = (wid >> 2) * 64, N0 = (wid & 3) * 32;

    if (MODE != 0 && tid < D) {
        b2s[tid] = b2[tid];
        if (MODE == 2) b1s[tid] = b1[tid];
    }

    // stage weights once
    {
        const uint4* s2h = (const uint4*)g_wh[w2_id];
        const uint4* s2l = (const uint4*)g_wl[w2_id];
        for (int i = tid; i < 128 * 16; i += 256) {
            int n = i >> 4, c = i & 15;
            *(uint4*)(W2h + n * ROWB + c * 16) = s2h[n * 16 + c];
            *(uint4*)(W2l + n * ROWB + c * 16) = s2l[n * 16 + c];
        }
        if (MODE == 2) {
            const uint4* s1h = (const uint4*)g_wh[w1_id];
            const uint4* s1l = (const uint4*)g_wl[w1_id];
            for (int i = tid; i < 128 * 16; i += 256) {
                int n = i >> 4, c = i & 15;
                *(uint4*)(W1h + n * ROWB + c * 16) = s1h[n * 16 + c];
                *(uint4*)(W1l + n * ROWB + c * 16) = s1l[n * 16 + c];
            }
        }
    }

    const uint32_t aOff = (uint32_t)(R0 + (lane & 15)) * ROWB + ((lane >> 4) * 16);
    const uint32_t bOff = (uint32_t)(N0 + (lane & 7)) * ROWB + (((lane >> 3) & 1) * 16);
    const uint32_t aH = smem_u32(Ah) + aOff, aL = smem_u32(Al) + aOff;
    const uint32_t w2H = smem_u32(W2h) + bOff, w2L = smem_u32(W2l) + bOff;
    const uint32_t w1H = (MODE == 2) ? smem_u32(W1h) + bOff : 0;
    const uint32_t w1L = (MODE == 2) ? smem_u32(W1l) + bOff : 0;

    for (int t = blockIdx.x; t < nTiles; t += gridDim.x) {
        const int row0 = t * TM;
        __syncthreads();

        // ---- fused aggregate + split-convert A tile (warp per row) ----
        for (int rr = wid; rr < TM; rr += 8) {
            const int gr = row0 + rr;
            float4 v = make_float4(0.f, 0.f, 0.f, 0.f);
            if (gr < nRows) {
                const int c4 = lane * 4;
                if (MODE == 0) {
                    v = *(const float4*)(x + (size_t)gr * D + c4);
                } else if (MODE == 1) {
                    int self = xidx[gr];
                    v = *(const float4*)(g_embT + (size_t)self * D + c4);
                    int e0 = g_rowptr[gr], e1 = g_rowptr[gr + 1];
                    for (int j = e0; j < e1; ++j) {
                        int ix = xidx[g_adj[j]];
                        float4 u = *(const float4*)(g_embT + (size_t)ix * D + c4);
                        v.x += u.x; v.y += u.y; v.z += u.z; v.w += u.w;
                    }
                    float4 bv = *(const float4*)(b1 + c4);
                    v.x = fmaxf(v.x + bv.x, 0.f); v.y = fmaxf(v.y + bv.y, 0.f);
                    v.z = fmaxf(v.z + bv.z, 0.f); v.w = fmaxf(v.w + bv.w, 0.f);
                } else {
                    v = *(const float4*)(x + (size_t)gr * D + c4);
                    int e0 = g_rowptr[gr], e1 = g_rowptr[gr + 1];
                    for (int j = e0; j < e1; ++j) {
                        int nb = g_adj[j];
                        float4 u = *(const float4*)(x + (size_t)nb * D + c4);
                        v.x += u.x; v.y += u.y; v.z += u.z; v.w += u.w;
                    }
                }
            }
            uint32_t h01 = pack_bf16(v.x, v.y), h23 = pack_bf16(v.z, v.w);
            float f0 = __uint_as_float(h01 << 16);
            float f1 = __uint_as_float(h01 & 0xffff0000u);
            float f2 = __uint_as_float(h23 << 16);
            float f3 = __uint_as_float(h23 & 0xffff0000u);
            *(uint2*)(Ah + rr * ROWB + lane * 8) = make_uint2(h01, h23);
            *(uint2*)(Al + rr * ROWB + lane * 8) =
                make_uint2(pack_bf16(v.x - f0, v.y - f1), pack_bf16(v.z - f2, v.w - f3));
        }
        __syncthreads();

        float acc[4][4][4];

        if (MODE == 2) {
            // phase 1: h = relu(A @ W1 + b1) -> back into Ah/Al
#pragma unroll
            for (int nt = 0; nt < 4; ++nt) {
                int c = N0 + nt * 8 + (lane & 3) * 2;
                float bb0 = b1s[c], bb1 = b1s[c + 1];
#pragma unroll
                for (int mt = 0; mt < 4; ++mt) {
                    acc[mt][nt][0] = bb0; acc[mt][nt][1] = bb1;
                    acc[mt][nt][2] = bb0; acc[mt][nt][3] = bb1;
                }
            }
            gemm_phase(aH, aL, w1H, w1L, acc);
            __syncthreads();
#pragma unroll
            for (int mt = 0; mt < 4; ++mt) {
#pragma unroll
                for (int nt = 0; nt < 4; ++nt) {
                    int r = R0 + mt * 16 + (lane >> 2);
                    int c = N0 + nt * 8 + (lane & 3) * 2;
                    float v0 = fmaxf(acc[mt][nt][0], 0.f), v1 = fmaxf(acc[mt][nt][1], 0.f);
                    float v2 = fmaxf(acc[mt][nt][2], 0.f), v3 = fmaxf(acc[mt][nt][3], 0.f);
                    uint32_t h01 = pack_bf16(v0, v1), h23 = pack_bf16(v2, v3);
                    float f0 = __uint_as_float(h01 << 16);
                    float f1 = __uint_as_float(h01 & 0xffff0000u);
                    float f2 = __uint_as_float(h23 << 16);
                    float f3 = __uint_as_float(h23 & 0xffff0000u);
                    *(uint32_t*)(Ah + r * ROWB + c * 2)       = h01;
                    *(uint32_t*)(Ah + (r + 8) * ROWB + c * 2) = h23;
                    *(uint32_t*)(Al + r * ROWB + c * 2)       = pack_bf16(v0 - f0, v1 - f1);
                    *(uint32_t*)(Al + (r + 8) * ROWB + c * 2) = pack_bf16(v2 - f2, v3 - f3);
                }
            }
            __syncthreads();
        }

        // phase 2
        if (MODE == 0) {
#pragma unroll
            for (int mt = 0; mt < 4; ++mt)
#pragma unroll
                for (int nt = 0; nt < 4; ++nt)
                    acc[mt][nt][0] = acc[mt][nt][1] = acc[mt][nt][2] = acc[mt][nt][3] = 0.f;
        } else {
#pragma unroll
            for (int nt = 0; nt < 4; ++nt) {
                int c = N0 + nt * 8 + (lane & 3) * 2;
                float bb0 = b2s[c], bb1 = b2s[c + 1];
#pragma unroll
                for (int mt = 0; mt < 4; ++mt) {
                    acc[mt][nt][0] = bb0; acc[mt][nt][1] = bb1;
                    acc[mt][nt][2] = bb0; acc[mt][nt][3] = bb1;
                }
            }
        }
        gemm_phase(aH, aL, w2H, w2L, acc);

        // ---- epilogue ----
#pragma unroll
        for (int mt = 0; mt < 4; ++mt) {
            int r = row0 + R0 + mt * 16 + (lane >> 2);
            int bi0 = 0, bi8 = 0;
            if (pbatch) {
                if (r < nRows)     bi0 = pbatch[r];
                if (r + 8 < nRows) bi8 = pbatch[r + 8];
            }
#pragma unroll
            for (int nt = 0; nt < 4; ++nt) {
                int c = N0 + nt * 8 + (lane & 3) * 2;
                float v0 = acc[mt][nt][0], v1 = acc[mt][nt][1];
                float v2 = acc[mt][nt][2], v3 = acc[mt][nt][3];
                if (MODE != 0) {
                    v0 = fmaxf(v0, 0.f); v1 = fmaxf(v1, 0.f);
                    v2 = fmaxf(v2, 0.f); v3 = fmaxf(v3, 0.f);
                }
                if (pbatch) {
                    if (r < nRows) {
                        float* p = g_pool + bi0 * D + c;
                        asm volatile("red.global.add.v2.f32 [%0], {%1, %2};"
                                     :: "l"(p), "f"(v0), "f"(v1) : "memory");
                    }
                    if (r + 8 < nRows) {
                        float* p = g_pool + bi8 * D + c;
                        asm volatile("red.global.add.v2.f32 [%0], {%1, %2};"
                                     :: "l"(p), "f"(v2), "f"(v3) : "memory");
                    }
                } else {
                    if (r < nRows)
                        *(float2*)(out + (size_t)r * D + c) = make_float2(v0, v1);
                    if (r + 8 < nRows)
                        *(float2*)(out + (size_t)(r + 8) * D + c) = make_float2(v2, v3);
                }
            }
        }
    }
}

// ---------------- classifier ------------------------------------------------
__global__ void classifier_kernel(const int* __restrict__ batch, int nNodes,
                                  const float* __restrict__ w1,
                                  const float* __restrict__ b1,
                                  const float* __restrict__ w2,
                                  const float* __restrict__ b2,
                                  float* __restrict__ out) {
    __shared__ float gs[D];
    __shared__ float hs[64];
    __shared__ float cnt_s;
    const int b = blockIdx.x;
    const int t = threadIdx.x;

    if (t == 0) {
        int lo = 0, hi = nNodes;
        while (lo < hi) { int m = (lo + hi) >> 1; if (batch[m] < b) lo = m + 1; else hi = m; }
        int start = lo;
        lo = start; hi = nNodes;
        while (lo < hi) { int m = (lo + hi) >> 1; if (batch[m] <= b) lo = m + 1; else hi = m; }
        cnt_s = fmaxf((float)(lo - start), 1.0f);
    }
    __syncthreads();

    gs[t] = g_pool[b * D + t] / cnt_s;
    __syncthreads();

    if (t < 64) {
        float h = b1[t];
#pragma unroll 8
        for (int k = 0; k < D; ++k) h += gs[k] * w1[k * 64 + t];
        hs[t] = fmaxf(h, 0.f);
    }
    __syncthreads();

    if (t == 0) {
        float o0 = b2[0], o1 = b2[1];
#pragma unroll 8
        for (int j = 0; j < 64; ++j) {
            o0 += hs[j] * w2[2 * j];
            o1 += hs[j] * w2[2 * j + 1];
        }
        float m = fmaxf(o0, o1);
        float e0 = expf(o0 - m), e1 = expf(o1 - m);
        float s = e0 + e1;
        out[2 * b]     = e0 / s;
        out[2 * b + 1] = e1 / s;
    }
}

// ---------------------------------------------------------------------------
extern "C" void kernel_launch(void* const* d_in, const int* in_sizes, int n_in,
                              void* d_out, int out_size) {
    const int*   x_idx   = (const int*)d_in[0];
    const int*   edge    = (const int*)d_in[1];
    const int*   batch   = (const int*)d_in[2];
    const float* emb     = (const float*)d_in[3];
    const float* conv_w1 = (const float*)d_in[4];
    const float* conv_b1 = (const float*)d_in[5];
    const float* conv_w2 = (const float*)d_in[6];
    const float* conv_b2 = (const float*)d_in[7];
    const float* mlp_w1  = (const float*)d_in[8];
    const float* mlp_b1  = (const float*)d_in[9];
    const float* mlp_w2  = (const float*)d_in[10];
    const float* mlp_b2  = (const float*)d_in[11];
    float* out = (float*)d_out;

    const int nNodes = in_sizes[0];
    const int nEdges = in_sizes[1] / 2;
    const int nVocab = in_sizes[3] / D;
    const int* src = edge;
    const int* dst = edge + nEdges;

    float *px, *py, *pembT;
    cudaGetSymbolAddress((void**)&px,    g_x);
    cudaGetSymbolAddress((void**)&py,    g_y);
    cudaGetSymbolAddress((void**)&pembT, g_embT);

    const int smem_small = 4 * TILE_B;   // 139264
    const int smem_big   = 6 * TILE_B;   // 208896
    cudaFuncSetAttribute(mlp_mma<0>, cudaFuncAttributeMaxDynamicSharedMemorySize, smem_small);
    cudaFuncSetAttribute(mlp_mma<1>, cudaFuncAttributeMaxDynamicSharedMemorySize, smem_small);
    cudaFuncSetAttribute(mlp_mma<2>, cudaFuncAttributeMaxDynamicSharedMemorySize, smem_big);

    const int nodeTiles = (nNodes + TM - 1) / TM;
    const int embTiles  = (nVocab + TM - 1) / TM;
    const int grid1 = nodeTiles < 148 ? nodeTiles : 148;
    const int gridE = embTiles  < 148 ? embTiles  : 148;

    // CSR build + zeros + weight prep
    zero_kernel<<<256, 256>>>();
    prep_weights<<<(6 * D * D + 255) / 256, 256>>>(conv_w1, conv_w2);
    hist_kernel<<<(nEdges + 255) / 256, 256>>>(dst, nEdges);
    scan_kernel<<<1, 1024>>>(nNodes);
    fill_kernel<<<(nEdges + 255) / 256, 256>>>(src, dst, nEdges);

    // embT = emb @ conv_w1[0]
    mlp_mma<0><<<gridE, 256, smem_small>>>(emb, nullptr, -1, 0, nullptr, nullptr,
                                           pembT, nullptr, nVocab, embTiles);

    // layer 0 (fused gather + aggregate): embT[x_idx] pull -> px
    mlp_mma<1><<<grid1, 256, smem_small>>>(nullptr, x_idx, -1, 3, conv_b1, conv_b2,
                                           px, nullptr, nNodes, nodeTiles);

    // layer 1: px -> py
    mlp_mma<2><<<grid1, 256, smem_big>>>(px, nullptr, 1, 4, conv_b1 + D, conv_b2 + D,
                                         py, nullptr, nNodes, nodeTiles);

    // layer 2: py -> pooled sums
    mlp_mma<2><<<grid1, 256, smem_big>>>(py, nullptr, 2, 5, conv_b1 + 2 * D,
                                         conv_b2 + 2 * D, nullptr, batch,
                                         nNodes, nodeTiles);

    // classifier + softmax
    classifier_kernel<<<N_GRAPHS, D>>>(batch, nNodes, mlp_w1, mlp_b1, mlp_w2,
                                       mlp_b2, out);
}

// round 7
// speedup vs baseline: 1.7259x; 1.7259x over previous
#include <cuda_runtime.h>
#include <cuda_bf16.h>
#include <math.h>
#include <stdint.h>

// Problem constants
#define N_NODES   100000
#define N_EDGES   600000
#define N_GRAPHS  1000
#define VOCAB     10000
#define D         128
#define TM        128              // rows per tile
#define ROWB      272              // padded smem row stride in bytes (136 bf16)
#define TILE_B    (128 * ROWB)     // 34816 bytes per 128x128 bf16 tile
#define NT_MLP    512              // threads per MLP CTA (16 warps)
#define SCAN_BLK  1024
#define NB_MAX    128

// ---------------- scratch -------------------------------------------------
__device__ float g_x[N_NODES * D];      // buffer A
__device__ float g_y[N_NODES * D];      // buffer B
__device__ float g_embT[VOCAB * D];
__device__ float g_pool[N_GRAPHS * D];
__device__ int   g_cnt[N_NODES];        // degree histogram
__device__ int   g_cur[N_NODES];        // fill cursors
__device__ int   g_rowptr[N_NODES + 1];
__device__ int   g_adj[N_EDGES];        // src node ids grouped by dst
__device__ int   g_bsum[NB_MAX];        // per-block sums
__device__ int   g_boff[NB_MAX];        // per-block exclusive offsets
// split-bf16 weights, transposed [n][k]; mats 0..2 = conv_w1[L], 3..5 = conv_w2[L]
__device__ __nv_bfloat16 g_wh[6][D * D];
__device__ __nv_bfloat16 g_wl[6][D * D];

// ---------------- helpers -------------------------------------------------
__device__ __forceinline__ uint32_t smem_u32(const void* p) {
    uint32_t a;
    asm("{ .reg .u64 t; cvta.to.shared.u64 t, %1; cvt.u32.u64 %0, t; }"
        : "=r"(a) : "l"(p));
    return a;
}

__device__ __forceinline__ uint32_t pack_bf16(float a, float b) {
    __nv_bfloat162 t;
    t.x = __float2bfloat16_rn(a);
    t.y = __float2bfloat16_rn(b);
    return *(uint32_t*)&t;
}

__device__ __forceinline__ void mma16816(float* d, uint32_t a0, uint32_t a1,
                                         uint32_t a2, uint32_t a3,
                                         uint32_t b0, uint32_t b1) {
    asm volatile(
        "mma.sync.aligned.m16n8k16.row.col.f32.bf16.bf16.f32 "
        "{%0,%1,%2,%3}, {%4,%5,%6,%7}, {%8,%9}, {%0,%1,%2,%3};\n"
        : "+f"(d[0]), "+f"(d[1]), "+f"(d[2]), "+f"(d[3])
        : "r"(a0), "r"(a1), "r"(a2), "r"(a3), "r"(b0), "r"(b1));
}

__device__ __forceinline__ void ldm_x4(uint32_t& r0, uint32_t& r1, uint32_t& r2,
                                       uint32_t& r3, uint32_t addr) {
    asm volatile("ldmatrix.sync.aligned.m8n8.x4.shared.b16 {%0,%1,%2,%3}, [%4];"
                 : "=r"(r0), "=r"(r1), "=r"(r2), "=r"(r3) : "r"(addr));
}

__device__ __forceinline__ void ldm_x2(uint32_t& r0, uint32_t& r1, uint32_t addr) {
    asm volatile("ldmatrix.sync.aligned.m8n8.x2.shared.b16 {%0,%1}, [%2];"
                 : "=r"(r0), "=r"(r1) : "r"(addr));
}

// ---------------- CSR build -------------------------------------------------
__global__ void zero_kernel() {
    int i = blockIdx.x * blockDim.x + threadIdx.x;
    int n = gridDim.x * blockDim.x;
    for (int j = i; j < N_NODES; j += n) g_cnt[j] = 0;
    for (int j = i; j < N_GRAPHS * D; j += n) g_pool[j] = 0.0f;
}

__global__ void hist_kernel(const int* __restrict__ dst, int nE) {
    int i = blockIdx.x * blockDim.x + threadIdx.x;
    if (i < nE) atomicAdd(&g_cnt[dst[i]], 1);
}

// phase A: per-block sums (coalesced)
__global__ void __launch_bounds__(SCAN_BLK, 1) scanA_kernel(int nNodes) {
    __shared__ int red[SCAN_BLK];
    int i = blockIdx.x * SCAN_BLK + threadIdx.x;
    int v = (i < nNodes) ? g_cnt[i] : 0;
    red[threadIdx.x] = v;
    __syncthreads();
    for (int off = SCAN_BLK / 2; off > 0; off >>= 1) {
        if (threadIdx.x < off) red[threadIdx.x] += red[threadIdx.x + off];
        __syncthreads();
    }
    if (threadIdx.x == 0) g_bsum[blockIdx.x] = red[0];
}

// phase B: exclusive scan of block sums (1 block)
__global__ void __launch_bounds__(NB_MAX, 1) scanB_kernel(int nb) {
    __shared__ int s[NB_MAX];
    int t = threadIdx.x;
    int v = (t < nb) ? g_bsum[t] : 0;
    s[t] = v;
    __syncthreads();
    for (int off = 1; off < NB_MAX; off <<= 1) {
        int u = (t >= off) ? s[t - off] : 0;
        __syncthreads();
        s[t] += u;
        __syncthreads();
    }
    if (t < nb) g_boff[t] = s[t] - v;     // exclusive
}

// phase C: per-block scan + write rowptr/cur
__global__ void __launch_bounds__(SCAN_BLK, 1) scanC_kernel(int nNodes) {
    __shared__ int s[SCAN_BLK];
    int i = blockIdx.x * SCAN_BLK + threadIdx.x;
    int t = threadIdx.x;
    int v = (i < nNodes) ? g_cnt[i] : 0;
    s[t] = v;
    __syncthreads();
    for (int off = 1; off < SCAN_BLK; off <<= 1) {
        int u = (t >= off) ? s[t - off] : 0;
        __syncthreads();
        s[t] += u;
        __syncthreads();
    }
    if (i < nNodes) {
        int excl = s[t] - v + g_boff[blockIdx.x];
        g_rowptr[i] = excl;
        g_cur[i] = excl;
        if (i == nNodes - 1) g_rowptr[nNodes] = excl + v;
    }
}

__global__ void fill_kernel(const int* __restrict__ src,
                            const int* __restrict__ dst, int nE) {
    int i = blockIdx.x * blockDim.x + threadIdx.x;
    if (i >= nE) return;
    int pos = atomicAdd(&g_cur[dst[i]], 1);
    g_adj[pos] = src[i];
}

// ---------------- weight prep -----------------------------------------------
__global__ void prep_weights(const float* __restrict__ w1,
                             const float* __restrict__ w2) {
    int i = blockIdx.x * blockDim.x + threadIdx.x;
    if (i >= 6 * D * D) return;
    int m = i / (D * D), kn = i % (D * D);
    int k = kn / D, n = kn % D;
    float v = (m < 3) ? w1[m * D * D + kn] : w2[(m - 3) * D * D + kn];
    __nv_bfloat16 h = __float2bfloat16_rn(v);
    __nv_bfloat16 l = __float2bfloat16_rn(v - __bfloat162float(h));
    g_wh[m][n * D + k] = h;
    g_wl[m][n * D + k] = l;
}

// ---------------- GEMM phase (per warp: 32x32 patch) ------------------------
__device__ __forceinline__ void gemm_phase(uint32_t aH, uint32_t aL,
                                           uint32_t bH, uint32_t bL,
                                           float (&acc)[2][4][4]) {
#pragma unroll
    for (int k0 = 0; k0 < D; k0 += 16) {
        uint32_t ah0[2], ah1[2], ah2[2], ah3[2];
        uint32_t al0[2], al1[2], al2[2], al3[2];
        uint32_t bh0[4], bh1[4], bl0[4], bl1[4];
#pragma unroll
        for (int mt = 0; mt < 2; ++mt) {
            ldm_x4(ah0[mt], ah1[mt], ah2[mt], ah3[mt], aH + mt * (16 * ROWB) + k0 * 2);
            ldm_x4(al0[mt], al1[mt], al2[mt], al3[mt], aL + mt * (16 * ROWB) + k0 * 2);
        }
#pragma unroll
        for (int nt = 0; nt < 4; ++nt) {
            ldm_x2(bh0[nt], bh1[nt], bH + nt * (8 * ROWB) + k0 * 2);
            ldm_x2(bl0[nt], bl1[nt], bL + nt * (8 * ROWB) + k0 * 2);
        }
#pragma unroll
        for (int mt = 0; mt < 2; ++mt) {
#pragma unroll
            for (int nt = 0; nt < 4; ++nt) {
                mma16816(acc[mt][nt], ah0[mt], ah1[mt], ah2[mt], ah3[mt], bh0[nt], bh1[nt]);
                mma16816(acc[mt][nt], ah0[mt], ah1[mt], ah2[mt], ah3[mt], bl0[nt], bl1[nt]);
                mma16816(acc[mt][nt], al0[mt], al1[mt], al2[mt], al3[mt], bh0[nt], bh1[nt]);
            }
        }
    }
}

// ---------------- persistent fused aggregate+MLP ----------------------------
// MODE 0: out = x @ W[w2_id]                      (plain rows, no agg)
// MODE 1: A = sum embT[x_idx[self+nbrs]]; h = relu(A + b1); out = relu(h@W2 + b2)
// MODE 2: A = x[self] + sum x[nbrs]; h = relu(A@W1 + b1); out = relu(h@W2 + b2)
// pbatch != nullptr: no out write; red.add result into g_pool[batch[row]].
template <int MODE>
__global__ void __launch_bounds__(NT_MLP, 1)
mlp_mma(const float* __restrict__ x, const int* __restrict__ xidx,
        int w1_id, int w2_id,
        const float* __restrict__ b1, const float* __restrict__ b2,
        float* __restrict__ out, const int* __restrict__ pbatch,
        int nRows, int nTiles) {
    extern __shared__ __align__(16) unsigned char sm[];
    unsigned char* Ah  = sm;
    unsigned char* Al  = sm + TILE_B;
    unsigned char* W2h = sm + 2 * TILE_B;
    unsigned char* W2l = sm + 3 * TILE_B;
    unsigned char* W1h = sm + 4 * TILE_B;   // MODE 2 only
    unsigned char* W1l = sm + 5 * TILE_B;
    __shared__ float b1s[D], b2s[D];

    const int tid  = threadIdx.x;
    const int lane = tid & 31, wid = tid >> 5;       // 16 warps
    const int R0 = (wid >> 2) * 32, N0 = (wid & 3) * 32;

    if (MODE != 0 && tid < D) {
        b2s[tid] = b2[tid];
        if (MODE == 2) b1s[tid] = b1[tid];
    }

    // stage weights once
    {
        const uint4* s2h = (const uint4*)g_wh[w2_id];
        const uint4* s2l = (const uint4*)g_wl[w2_id];
        for (int i = tid; i < 128 * 16; i += NT_MLP) {
            int n = i >> 4, c = i & 15;
            *(uint4*)(W2h + n * ROWB + c * 16) = s2h[n * 16 + c];
            *(uint4*)(W2l + n * ROWB + c * 16) = s2l[n * 16 + c];
        }
        if (MODE == 2) {
            const uint4* s1h = (const uint4*)g_wh[w1_id];
            const uint4* s1l = (const uint4*)g_wl[w1_id];
            for (int i = tid; i < 128 * 16; i += NT_MLP) {
                int n = i >> 4, c = i & 15;
                *(uint4*)(W1h + n * ROWB + c * 16) = s1h[n * 16 + c];
                *(uint4*)(W1l + n * ROWB + c * 16) = s1l[n * 16 + c];
            }
        }
    }

    const uint32_t aOff = (uint32_t)(R0 + (lane & 15)) * ROWB + ((lane >> 4) * 16);
    const uint32_t bOff = (uint32_t)(N0 + (lane & 7)) * ROWB + (((lane >> 3) & 1) * 16);
    const uint32_t aH = smem_u32(Ah) + aOff, aL = smem_u32(Al) + aOff;
    const uint32_t w2H = smem_u32(W2h) + bOff, w2L = smem_u32(W2l) + bOff;
    const uint32_t w1H = (MODE == 2) ? smem_u32(W1h) + bOff : 0;
    const uint32_t w1L = (MODE == 2) ? smem_u32(W1l) + bOff : 0;

    for (int t = blockIdx.x; t < nTiles; t += gridDim.x) {
        const int row0 = t * TM;
        __syncthreads();

        // ---- fused aggregate + split-convert A tile (warp per row) ----
        for (int rr = wid; rr < TM; rr += 16) {
            const int gr = row0 + rr;
            float4 v = make_float4(0.f, 0.f, 0.f, 0.f);
            if (gr < nRows) {
                const int c4 = lane * 4;
                if (MODE == 0) {
                    v = *(const float4*)(x + (size_t)gr * D + c4);
                } else if (MODE == 1) {
                    int self = xidx[gr];
                    v = *(const float4*)(g_embT + (size_t)self * D + c4);
                    int e0 = g_rowptr[gr], e1 = g_rowptr[gr + 1];
                    for (int j = e0; j < e1; ++j) {
                        int ix = xidx[g_adj[j]];
                        float4 u = *(const float4*)(g_embT + (size_t)ix * D + c4);
                        v.x += u.x; v.y += u.y; v.z += u.z; v.w += u.w;
                    }
                    float4 bv = *(const float4*)(b1 + c4);
                    v.x = fmaxf(v.x + bv.x, 0.f); v.y = fmaxf(v.y + bv.y, 0.f);
                    v.z = fmaxf(v.z + bv.z, 0.f); v.w = fmaxf(v.w + bv.w, 0.f);
                } else {
                    v = *(const float4*)(x + (size_t)gr * D + c4);
                    int e0 = g_rowptr[gr], e1 = g_rowptr[gr + 1];
                    for (int j = e0; j < e1; ++j) {
                        int nb = g_adj[j];
                        float4 u = *(const float4*)(x + (size_t)nb * D + c4);
                        v.x += u.x; v.y += u.y; v.z += u.z; v.w += u.w;
                    }
                }
            }
            uint32_t h01 = pack_bf16(v.x, v.y), h23 = pack_bf16(v.z, v.w);
            float f0 = __uint_as_float(h01 << 16);
            float f1 = __uint_as_float(h01 & 0xffff0000u);
            float f2 = __uint_as_float(h23 << 16);
            float f3 = __uint_as_float(h23 & 0xffff0000u);
            *(uint2*)(Ah + rr * ROWB + lane * 8) = make_uint2(h01, h23);
            *(uint2*)(Al + rr * ROWB + lane * 8) =
                make_uint2(pack_bf16(v.x - f0, v.y - f1), pack_bf16(v.z - f2, v.w - f3));
        }
        __syncthreads();

        float acc[2][4][4];

        if (MODE == 2) {
            // phase 1: h = relu(A @ W1 + b1) -> back into Ah/Al
#pragma unroll
            for (int nt = 0; nt < 4; ++nt) {
                int c = N0 + nt * 8 + (lane & 3) * 2;
                float bb0 = b1s[c], bb1 = b1s[c + 1];
#pragma unroll
                for (int mt = 0; mt < 2; ++mt) {
                    acc[mt][nt][0] = bb0; acc[mt][nt][1] = bb1;
                    acc[mt][nt][2] = bb0; acc[mt][nt][3] = bb1;
                }
            }
            gemm_phase(aH, aL, w1H, w1L, acc);
            __syncthreads();
#pragma unroll
            for (int mt = 0; mt < 2; ++mt) {
#pragma unroll
                for (int nt = 0; nt < 4; ++nt) {
                    int r = R0 + mt * 16 + (lane >> 2);
                    int c = N0 + nt * 8 + (lane & 3) * 2;
                    float v0 = fmaxf(acc[mt][nt][0], 0.f), v1 = fmaxf(acc[mt][nt][1], 0.f);
                    float v2 = fmaxf(acc[mt][nt][2], 0.f), v3 = fmaxf(acc[mt][nt][3], 0.f);
                    uint32_t h01 = pack_bf16(v0, v1), h23 = pack_bf16(v2, v3);
                    float f0 = __uint_as_float(h01 << 16);
                    float f1 = __uint_as_float(h01 & 0xffff0000u);
                    float f2 = __uint_as_float(h23 << 16);
                    float f3 = __uint_as_float(h23 & 0xffff0000u);
                    *(uint32_t*)(Ah + r * ROWB + c * 2)       = h01;
                    *(uint32_t*)(Ah + (r + 8) * ROWB + c * 2) = h23;
                    *(uint32_t*)(Al + r * ROWB + c * 2)       = pack_bf16(v0 - f0, v1 - f1);
                    *(uint32_t*)(Al + (r + 8) * ROWB + c * 2) = pack_bf16(v2 - f2, v3 - f3);
                }
            }
            __syncthreads();
        }

        // phase 2
        if (MODE == 0) {
#pragma unroll
            for (int mt = 0; mt < 2; ++mt)
#pragma unroll
                for (int nt = 0; nt < 4; ++nt)
                    acc[mt][nt][0] = acc[mt][nt][1] = acc[mt][nt][2] = acc[mt][nt][3] = 0.f;
        } else {
#pragma unroll
            for (int nt = 0; nt < 4; ++nt) {
                int c = N0 + nt * 8 + (lane & 3) * 2;
                float bb0 = b2s[c], bb1 = b2s[c + 1];
#pragma unroll
                for (int mt = 0; mt < 2; ++mt) {
                    acc[mt][nt][0] = bb0; acc[mt][nt][1] = bb1;
                    acc[mt][nt][2] = bb0; acc[mt][nt][3] = bb1;
                }
            }
        }
        gemm_phase(aH, aL, w2H, w2L, acc);

        // ---- epilogue ----
#pragma unroll
        for (int mt = 0; mt < 2; ++mt) {
            int r = row0 + R0 + mt * 16 + (lane >> 2);
            int bi0 = 0, bi8 = 0;
            if (pbatch) {
                if (r < nRows)     bi0 = pbatch[r];
                if (r + 8 < nRows) bi8 = pbatch[r + 8];
            }
#pragma unroll
            for (int nt = 0; nt < 4; ++nt) {
                int c = N0 + nt * 8 + (lane & 3) * 2;
                float v0 = acc[mt][nt][0], v1 = acc[mt][nt][1];
                float v2 = acc[mt][nt][2], v3 = acc[mt][nt][3];
                if (MODE != 0) {
                    v0 = fmaxf(v0, 0.f); v1 = fmaxf(v1, 0.f);
                    v2 = fmaxf(v2, 0.f); v3 = fmaxf(v3, 0.f);
                }
                if (pbatch) {
                    if (r < nRows) {
                        float* p = g_pool + bi0 * D + c;
                        asm volatile("red.global.add.v2.f32 [%0], {%1, %2};"
                                     :: "l"(p), "f"(v0), "f"(v1) : "memory");
                    }
                    if (r + 8 < nRows) {
                        float* p = g_pool + bi8 * D + c;
                        asm volatile("red.global.add.v2.f32 [%0], {%1, %2};"
                                     :: "l"(p), "f"(v2), "f"(v3) : "memory");
                    }
                } else {
                    if (r < nRows)
                        *(float2*)(out + (size_t)r * D + c) = make_float2(v0, v1);
                    if (r + 8 < nRows)
                        *(float2*)(out + (size_t)(r + 8) * D + c) = make_float2(v2, v3);
                }
            }
        }
    }
}

// ---------------- classifier ------------------------------------------------
__global__ void classifier_kernel(const int* __restrict__ batch, int nNodes,
                                  const float* __restrict__ w1,
                                  const float* __restrict__ b1,
                                  const float* __restrict__ w2,
                                  const float* __restrict__ b2,
                                  float* __restrict__ out) {
    __shared__ float gs[D];
    __shared__ float hs[64];
    __shared__ float cnt_s;
    const int b = blockIdx.x;
    const int t = threadIdx.x;

    if (t == 0) {
        int lo = 0, hi = nNodes;
        while (lo < hi) { int m = (lo + hi) >> 1; if (batch[m] < b) lo = m + 1; else hi = m; }
        int start = lo;
        lo = start; hi = nNodes;
        while (lo < hi) { int m = (lo + hi) >> 1; if (batch[m] <= b) lo = m + 1; else hi = m; }
        cnt_s = fmaxf((float)(lo - start), 1.0f);
    }
    __syncthreads();

    gs[t] = g_pool[b * D + t] / cnt_s;
    __syncthreads();

    if (t < 64) {
        float h = b1[t];
#pragma unroll 8
        for (int k = 0; k < D; ++k) h += gs[k] * w1[k * 64 + t];
        hs[t] = fmaxf(h, 0.f);
    }
    __syncthreads();

    if (t == 0) {
        float o0 = b2[0], o1 = b2[1];
#pragma unroll 8
        for (int j = 0; j < 64; ++j) {
            o0 += hs[j] * w2[2 * j];
            o1 += hs[j] * w2[2 * j + 1];
        }
        float m = fmaxf(o0, o1);
        float e0 = expf(o0 - m), e1 = expf(o1 - m);
        float s = e0 + e1;
        out[2 * b]     = e0 / s;
        out[2 * b + 1] = e1 / s;
    }
}

// ---------------------------------------------------------------------------
extern "C" void kernel_launch(void* const* d_in, const int* in_sizes, int n_in,
                              void* d_out, int out_size) {
    const int*   x_idx   = (const int*)d_in[0];
    const int*   edge    = (const int*)d_in[1];
    const int*   batch   = (const int*)d_in[2];
    const float* emb     = (const float*)d_in[3];
    const float* conv_w1 = (const float*)d_in[4];
    const float* conv_b1 = (const float*)d_in[5];
    const float* conv_w2 = (const float*)d_in[6];
    const float* conv_b2 = (const float*)d_in[7];
    const float* mlp_w1  = (const float*)d_in[8];
    const float* mlp_b1  = (const float*)d_in[9];
    const float* mlp_w2  = (const float*)d_in[10];
    const float* mlp_b2  = (const float*)d_in[11];
    float* out = (float*)d_out;

    const int nNodes = in_sizes[0];
    const int nEdges = in_sizes[1] / 2;
    const int nVocab = in_sizes[3] / D;
    const int* src = edge;
    const int* dst = edge + nEdges;

    float *px, *py, *pembT;
    cudaGetSymbolAddress((void**)&px,    g_x);
    cudaGetSymbolAddress((void**)&py,    g_y);
    cudaGetSymbolAddress((void**)&pembT, g_embT);

    const int smem_small = 4 * TILE_B;   // 139264
    const int smem_big   = 6 * TILE_B;   // 208896
    cudaFuncSetAttribute(mlp_mma<0>, cudaFuncAttributeMaxDynamicSharedMemorySize, smem_small);
    cudaFuncSetAttribute(mlp_mma<1>, cudaFuncAttributeMaxDynamicSharedMemorySize, smem_small);
    cudaFuncSetAttribute(mlp_mma<2>, cudaFuncAttributeMaxDynamicSharedMemorySize, smem_big);

    const int nodeTiles = (nNodes + TM - 1) / TM;
    const int embTiles  = (nVocab + TM - 1) / TM;
    const int grid1 = nodeTiles < 148 ? nodeTiles : 148;
    const int gridE = embTiles  < 148 ? embTiles  : 148;
    const int nb = (nNodes + SCAN_BLK - 1) / SCAN_BLK;   // 98 <= NB_MAX

    // CSR build + zeros + weight prep
    zero_kernel<<<256, 256>>>();
    prep_weights<<<(6 * D * D + 255) / 256, 256>>>(conv_w1, conv_w2);
    hist_kernel<<<(nEdges + 255) / 256, 256>>>(dst, nEdges);
    scanA_kernel<<<nb, SCAN_BLK>>>(nNodes);
    scanB_kernel<<<1, NB_MAX>>>(nb);
    scanC_kernel<<<nb, SCAN_BLK>>>(nNodes);
    fill_kernel<<<(nEdges + 255) / 256, 256>>>(src, dst, nEdges);

    // embT = emb @ conv_w1[0]
    mlp_mma<0><<<gridE, NT_MLP, smem_small>>>(emb, nullptr, -1, 0, nullptr, nullptr,
                                              pembT, nullptr, nVocab, embTiles);

    // layer 0 (fused gather + aggregate): embT[x_idx] pull -> px
    mlp_mma<1><<<grid1, NT_MLP, smem_small>>>(nullptr, x_idx, -1, 3, conv_b1, conv_b2,
                                              px, nullptr, nNodes, nodeTiles);

    // layer 1: px -> py
    mlp_mma<2><<<grid1, NT_MLP, smem_big>>>(px, nullptr, 1, 4, conv_b1 + D, conv_b2 + D,
                                            py, nullptr, nNodes, nodeTiles);

    // layer 2: py -> pooled sums
    mlp_mma<2><<<grid1, NT_MLP, smem_big>>>(py, nullptr, 2, 5, conv_b1 + 2 * D,
                                            conv_b2 + 2 * D, nullptr, batch,
                                            nNodes, nodeTiles);

    // classifier + softmax
    classifier_kernel<<<N_GRAPHS, D>>>(batch, nNodes, mlp_w1, mlp_b1, mlp_w2,
                                       mlp_b2, out);
}

// round 9
// speedup vs baseline: 1.8039x; 1.0452x over previous
#include <cuda_runtime.h>
#include <cuda_bf16.h>
#include <math.h>
#include <stdint.h>

// Problem constants
#define N_NODES   100000
#define N_EDGES   600000
#define N_GRAPHS  1000
#define VOCAB     10000
#define D         128
#define TMG       64               // rows per GROUP tile
#define ROWB      272              // padded smem row stride in bytes (136 bf16)
#define TILE_B    (128 * ROWB)     // full 128-row buffer (two 64-row group halves)
#define HALF_B    (64 * ROWB)
#define NT_MLP    512              // 16 warps: 2 groups x 8 warps
#define SCAN_BLK  1024
#define NB_MAX    128

// ---------------- scratch -------------------------------------------------
__device__ float g_x[N_NODES * D];
__device__ float g_y[N_NODES * D];
__device__ float g_embT[VOCAB * D];
__device__ float g_pool[N_GRAPHS * D];
__device__ int   g_cnt[N_NODES];
__device__ int   g_cur[N_NODES];
__device__ int   g_rowptr[N_NODES + 1];
__device__ int   g_adj[N_EDGES];
__device__ int   g_bsum[NB_MAX];
__device__ int   g_boff[NB_MAX];
// split-bf16 weights, transposed [n][k]; mats 0..2 = conv_w1[L], 3..5 = conv_w2[L]
__device__ __nv_bfloat16 g_wh[6][D * D];
__device__ __nv_bfloat16 g_wl[6][D * D];

// ---------------- helpers -------------------------------------------------
__device__ __forceinline__ uint32_t smem_u32(const void* p) {
    uint32_t a;
    asm("{ .reg .u64 t; cvta.to.shared.u64 t, %1; cvt.u32.u64 %0, t; }"
        : "=r"(a) : "l"(p));
    return a;
}

__device__ __forceinline__ uint32_t pack_bf16(float a, float b) {
    __nv_bfloat162 t;
    t.x = __float2bfloat16_rn(a);
    t.y = __float2bfloat16_rn(b);
    return *(uint32_t*)&t;
}

__device__ __forceinline__ void mma16816(float* d, uint32_t a0, uint32_t a1,
                                         uint32_t a2, uint32_t a3,
                                         uint32_t b0, uint32_t b1) {
    asm volatile(
        "mma.sync.aligned.m16n8k16.row.col.f32.bf16.bf16.f32 "
        "{%0,%1,%2,%3}, {%4,%5,%6,%7}, {%8,%9}, {%0,%1,%2,%3};\n"
        : "+f"(d[0]), "+f"(d[1]), "+f"(d[2]), "+f"(d[3])
        : "r"(a0), "r"(a1), "r"(a2), "r"(a3), "r"(b0), "r"(b1));
}

__device__ __forceinline__ void ldm_x4(uint32_t& r0, uint32_t& r1, uint32_t& r2,
                                       uint32_t& r3, uint32_t addr) {
    asm volatile("ldmatrix.sync.aligned.m8n8.x4.shared.b16 {%0,%1,%2,%3}, [%4];"
                 : "=r"(r0), "=r"(r1), "=r"(r2), "=r"(r3) : "r"(addr));
}

__device__ __forceinline__ void ldm_x2(uint32_t& r0, uint32_t& r1, uint32_t addr) {
    asm volatile("ldmatrix.sync.aligned.m8n8.x2.shared.b16 {%0,%1}, [%2];"
                 : "=r"(r0), "=r"(r1) : "r"(addr));
}

__device__ __forceinline__ void group_bar(int g) {
    asm volatile("bar.sync %0, %1;" :: "r"(g + 1), "r"(256) : "memory");
}

// ---------------- CSR build -------------------------------------------------
__global__ void zero_kernel() {
    int i = blockIdx.x * blockDim.x + threadIdx.x;
    int n = gridDim.x * blockDim.x;
    for (int j = i; j < N_NODES; j += n) g_cnt[j] = 0;
    for (int j = i; j < N_GRAPHS * D; j += n) g_pool[j] = 0.0f;
}

__global__ void hist_kernel(const int* __restrict__ dst, int nE) {
    int i = blockIdx.x * blockDim.x + threadIdx.x;
    if (i < nE) atomicAdd(&g_cnt[dst[i]], 1);
}

__global__ void __launch_bounds__(SCAN_BLK, 1) scanA_kernel(int nNodes) {
    __shared__ int red[SCAN_BLK];
    int i = blockIdx.x * SCAN_BLK + threadIdx.x;
    int v = (i < nNodes) ? g_cnt[i] : 0;
    red[threadIdx.x] = v;
    __syncthreads();
    for (int off = SCAN_BLK / 2; off > 0; off >>= 1) {
        if (threadIdx.x < off) red[threadIdx.x] += red[threadIdx.x + off];
        __syncthreads();
    }
    if (threadIdx.x == 0) g_bsum[blockIdx.x] = red[0];
}

__global__ void __launch_bounds__(NB_MAX, 1) scanB_kernel(int nb) {
    __shared__ int s[NB_MAX];
    int t = threadIdx.x;
    int v = (t < nb) ? g_bsum[t] : 0;
    s[t] = v;
    __syncthreads();
    for (int off = 1; off < NB_MAX; off <<= 1) {
        int u = (t >= off) ? s[t - off] : 0;
        __syncthreads();
        s[t] += u;
        __syncthreads();
    }
    if (t < nb) g_boff[t] = s[t] - v;
}

__global__ void __launch_bounds__(SCAN_BLK, 1) scanC_kernel(int nNodes) {
    __shared__ int s[SCAN_BLK];
    int i = blockIdx.x * SCAN_BLK + threadIdx.x;
    int t = threadIdx.x;
    int v = (i < nNodes) ? g_cnt[i] : 0;
    s[t] = v;
    __syncthreads();
    for (int off = 1; off < SCAN_BLK; off <<= 1) {
        int u = (t >= off) ? s[t - off] : 0;
        __syncthreads();
        s[t] += u;
        __syncthreads();
    }
    if (i < nNodes) {
        int excl = s[t] - v + g_boff[blockIdx.x];
        g_rowptr[i] = excl;
        g_cur[i] = excl;
        if (i == nNodes - 1) g_rowptr[nNodes] = excl + v;
    }
}

__global__ void fill_kernel(const int* __restrict__ src,
                            const int* __restrict__ dst, int nE) {
    int i = blockIdx.x * blockDim.x + threadIdx.x;
    if (i >= nE) return;
    int pos = atomicAdd(&g_cur[dst[i]], 1);
    g_adj[pos] = src[i];
}

// ---------------- weight prep -----------------------------------------------
__global__ void prep_weights(const float* __restrict__ w1,
                             const float* __restrict__ w2) {
    int i = blockIdx.x * blockDim.x + threadIdx.x;
    if (i >= 6 * D * D) return;
    int m = i / (D * D), kn = i % (D * D);
    int k = kn / D, n = kn % D;
    float v = (m < 3) ? w1[m * D * D + kn] : w2[(m - 3) * D * D + kn];
    __nv_bfloat16 h = __float2bfloat16_rn(v);
    __nv_bfloat16 l = __float2bfloat16_rn(v - __bfloat162float(h));
    g_wh[m][n * D + k] = h;
    g_wl[m][n * D + k] = l;
}

// ---------------- GEMM phase (per warp: 32x32 patch of a 64-row tile) -------
__device__ __forceinline__ void gemm_phase(uint32_t aH, uint32_t aL,
                                           uint32_t bH, uint32_t bL,
                                           float (&acc)[2][4][4]) {
#pragma unroll
    for (int k0 = 0; k0 < D; k0 += 16) {
        uint32_t ah0[2], ah1[2], ah2[2], ah3[2];
        uint32_t al0[2], al1[2], al2[2], al3[2];
        uint32_t bh0[4], bh1[4], bl0[4], bl1[4];
#pragma unroll
        for (int mt = 0; mt < 2; ++mt) {
            ldm_x4(ah0[mt], ah1[mt], ah2[mt], ah3[mt], aH + mt * (16 * ROWB) + k0 * 2);
            ldm_x4(al0[mt], al1[mt], al2[mt], al3[mt], aL + mt * (16 * ROWB) + k0 * 2);
        }
#pragma unroll
        for (int nt = 0; nt < 4; ++nt) {
            ldm_x2(bh0[nt], bh1[nt], bH + nt * (8 * ROWB) + k0 * 2);
            ldm_x2(bl0[nt], bl1[nt], bL + nt * (8 * ROWB) + k0 * 2);
        }
#pragma unroll
        for (int mt = 0; mt < 2; ++mt) {
#pragma unroll
            for (int nt = 0; nt < 4; ++nt) {
                mma16816(acc[mt][nt], ah0[mt], ah1[mt], ah2[mt], ah3[mt], bh0[nt], bh1[nt]);
                mma16816(acc[mt][nt], ah0[mt], ah1[mt], ah2[mt], ah3[mt], bl0[nt], bl1[nt]);
                mma16816(acc[mt][nt], al0[mt], al1[mt], al2[mt], al3[mt], bh0[nt], bh1[nt]);
            }
        }
    }
}

// ---------------- persistent fused aggregate+MLP, 2 groups per CTA ----------
// MODE 0: out = x @ W[w2_id]
// MODE 1: A = sum embT[x_idx[self+nbrs]]; h = relu(A + b1); out = relu(h@W2 + b2)
// MODE 2: A = x[self] + sum x[nbrs]; h = relu(A@W1 + b1); out = relu(h@W2 + b2)
// pbatch != nullptr: red.add result into g_pool[batch[row]] instead of out.
template <int MODE>
__global__ void __launch_bounds__(NT_MLP, 1)
mlp_mma(const float* __restrict__ x, const int* __restrict__ xidx,
        int w1_id, int w2_id,
        const float* __restrict__ b1, const float* __restrict__ b2,
        float* __restrict__ out, const int* __restrict__ pbatch,
        int nRows, int nTiles) {
    extern __shared__ __align__(16) unsigned char sm[];
    unsigned char* Ah  = sm;                 // 128 rows: group g owns rows [64g, 64g+64)
    unsigned char* Al  = sm + TILE_B;
    unsigned char* W2h = sm + 2 * TILE_B;
    unsigned char* W2l = sm + 3 * TILE_B;
    unsigned char* W1h = sm + 4 * TILE_B;    // MODE 2 only
    unsigned char* W1l = sm + 5 * TILE_B;
    __shared__ float b1s[D], b2s[D];

    const int tid  = threadIdx.x;
    const int lane = tid & 31, wid = tid >> 5;
    const int g    = wid >> 3;               // group 0 / 1
    const int wg   = wid & 7;                // warp within group
    const int R0 = (wg >> 2) * 32, N0 = (wg & 3) * 32;

    if (MODE != 0 && tid < D) {
        b2s[tid] = b2[tid];
        if (MODE == 2) b1s[tid] = b1[tid];
    }

    // stage weights once (all 16 warps)
    {
        const uint4* s2h = (const uint4*)g_wh[w2_id];
        const uint4* s2l = (const uint4*)g_wl[w2_id];
        for (int i = tid; i < 128 * 16; i += NT_MLP) {
            int n = i >> 4, c = i & 15;
            *(uint4*)(W2h + n * ROWB + c * 16) = s2h[n * 16 + c];
            *(uint4*)(W2l + n * ROWB + c * 16) = s2l[n * 16 + c];
        }
        if (MODE == 2) {
            const uint4* s1h = (const uint4*)g_wh[w1_id];
            const uint4* s1l = (const uint4*)g_wl[w1_id];
            for (int i = tid; i < 128 * 16; i += NT_MLP) {
                int n = i >> 4, c = i & 15;
                *(uint4*)(W1h + n * ROWB + c * 16) = s1h[n * 16 + c];
                *(uint4*)(W1l + n * ROWB + c * 16) = s1l[n * 16 + c];
            }
        }
    }
    __syncthreads();     // weights visible to both groups; last full-CTA barrier

    // group-local A-half base and per-lane addresses
    unsigned char* AhG = Ah + g * HALF_B;
    unsigned char* AlG = Al + g * HALF_B;
    const uint32_t aOff = (uint32_t)(R0 + (lane & 15)) * ROWB + ((lane >> 4) * 16);
    const uint32_t bOff = (uint32_t)(N0 + (lane & 7)) * ROWB + (((lane >> 3) & 1) * 16);
    const uint32_t aH = smem_u32(AhG) + aOff, aL = smem_u32(AlG) + aOff;
    const uint32_t w2H = smem_u32(W2h) + bOff, w2L = smem_u32(W2l) + bOff;
    const uint32_t w1H = (MODE == 2) ? smem_u32(W1h) + bOff : 0;
    const uint32_t w1L = (MODE == 2) ? smem_u32(W1l) + bOff : 0;

    for (int t = blockIdx.x * 2 + g; t < nTiles; t += gridDim.x * 2) {
        const int row0 = t * TMG;
        group_bar(g);   // protect this group's A half from previous iteration

        // ---- fused aggregate + split-convert A half (warp per row) ----
        for (int rr = wg; rr < TMG; rr += 8) {
            const int gr = row0 + rr;
            float4 v = make_float4(0.f, 0.f, 0.f, 0.f);
            if (gr < nRows) {
                const int c4 = lane * 4;
                if (MODE == 0) {
                    v = *(const float4*)(x + (size_t)gr * D + c4);
                } else if (MODE == 1) {
                    int self = xidx[gr];
                    v = *(const float4*)(g_embT + (size_t)self * D + c4);
                    int e0 = g_rowptr[gr], e1 = g_rowptr[gr + 1];
                    for (int j = e0; j < e1; ++j) {
                        int ix = xidx[g_adj[j]];
                        float4 u = *(const float4*)(g_embT + (size_t)ix * D + c4);
                        v.x += u.x; v.y += u.y; v.z += u.z; v.w += u.w;
                    }
                    float4 bv = *(const float4*)(b1 + c4);
                    v.x = fmaxf(v.x + bv.x, 0.f); v.y = fmaxf(v.y + bv.y, 0.f);
                    v.z = fmaxf(v.z + bv.z, 0.f); v.w = fmaxf(v.w + bv.w, 0.f);
                } else {
                    v = *(const float4*)(x + (size_t)gr * D + c4);
                    int e0 = g_rowptr[gr], e1 = g_rowptr[gr + 1];
                    for (int j = e0; j < e1; ++j) {
                        int nb = g_adj[j];
                        float4 u = *(const float4*)(x + (size_t)nb * D + c4);
                        v.x += u.x; v.y += u.y; v.z += u.z; v.w += u.w;
                    }
                }
            }
            uint32_t h01 = pack_bf16(v.x, v.y), h23 = pack_bf16(v.z, v.w);
            float f0 = __uint_as_float(h01 << 16);
            float f1 = __uint_as_float(h01 & 0xffff0000u);
            float f2 = __uint_as_float(h23 << 16);
            float f3 = __uint_as_float(h23 & 0xffff0000u);
            *(uint2*)(AhG + rr * ROWB + lane * 8) = make_uint2(h01, h23);
            *(uint2*)(AlG + rr * ROWB + lane * 8) =
                make_uint2(pack_bf16(v.x - f0, v.y - f1), pack_bf16(v.z - f2, v.w - f3));
        }
        group_bar(g);

        float acc[2][4][4];

        if (MODE == 2) {
            // phase 1: h = relu(A @ W1 + b1) -> back into AhG/AlG
#pragma unroll
            for (int nt = 0; nt < 4; ++nt) {
                int c = N0 + nt * 8 + (lane & 3) * 2;
                float bb0 = b1s[c], bb1 = b1s[c + 1];
#pragma unroll
                for (int mt = 0; mt < 2; ++mt) {
                    acc[mt][nt][0] = bb0; acc[mt][nt][1] = bb1;
                    acc[mt][nt][2] = bb0; acc[mt][nt][3] = bb1;
                }
            }
            gemm_phase(aH, aL, w1H, w1L, acc);
            group_bar(g);
#pragma unroll
            for (int mt = 0; mt < 2; ++mt) {
#pragma unroll
                for (int nt = 0; nt < 4; ++nt) {
                    int r = R0 + mt * 16 + (lane >> 2);
                    int c = N0 + nt * 8 + (lane & 3) * 2;
                    float v0 = fmaxf(acc[mt][nt][0], 0.f), v1 = fmaxf(acc[mt][nt][1], 0.f);
                    float v2 = fmaxf(acc[mt][nt][2], 0.f), v3 = fmaxf(acc[mt][nt][3], 0.f);
                    uint32_t h01 = pack_bf16(v0, v1), h23 = pack_bf16(v2, v3);
                    float f0 = __uint_as_float(h01 << 16);
                    float f1 = __uint_as_float(h01 & 0xffff0000u);
                    float f2 = __uint_as_float(h23 << 16);
                    float f3 = __uint_as_float(h23 & 0xffff0000u);
                    *(uint32_t*)(AhG + r * ROWB + c * 2)       = h01;
                    *(uint32_t*)(AhG + (r + 8) * ROWB + c * 2) = h23;
                    *(uint32_t*)(AlG + r * ROWB + c * 2)       = pack_bf16(v0 - f0, v1 - f1);
                    *(uint32_t*)(AlG + (r + 8) * ROWB + c * 2) = pack_bf16(v2 - f2, v3 - f3);
                }
            }
            group_bar(g);
        }

        // phase 2
        if (MODE == 0) {
#pragma unroll
            for (int mt = 0; mt < 2; ++mt)
#pragma unroll
                for (int nt = 0; nt < 4; ++nt)
                    acc[mt][nt][0] = acc[mt][nt][1] = acc[mt][nt][2] = acc[mt][nt][3] = 0.f;
        } else {
#pragma unroll
            for (int nt = 0; nt < 4; ++nt) {
                int c = N0 + nt * 8 + (lane & 3) * 2;
                float bb0 = b2s[c], bb1 = b2s[c + 1];
#pragma unroll
                for (int mt = 0; mt < 2; ++mt) {
                    acc[mt][nt][0] = bb0; acc[mt][nt][1] = bb1;
                    acc[mt][nt][2] = bb0; acc[mt][nt][3] = bb1;
                }
            }
        }
        gemm_phase(aH, aL, w2H, w2L, acc);

        // ---- epilogue ----
#pragma unroll
        for (int mt = 0; mt < 2; ++mt) {
            int r = row0 + R0 + mt * 16 + (lane >> 2);
            int bi0 = 0, bi8 = 0;
            if (pbatch) {
                if (r < nRows)     bi0 = pbatch[r];
                if (r + 8 < nRows) bi8 = pbatch[r + 8];
            }
#pragma unroll
            for (int nt = 0; nt < 4; ++nt) {
                int c = N0 + nt * 8 + (lane & 3) * 2;
                float v0 = acc[mt][nt][0], v1 = acc[mt][nt][1];
                float v2 = acc[mt][nt][2], v3 = acc[mt][nt][3];
                if (MODE != 0) {
                    v0 = fmaxf(v0, 0.f); v1 = fmaxf(v1, 0.f);
                    v2 = fmaxf(v2, 0.f); v3 = fmaxf(v3, 0.f);
                }
                if (pbatch) {
                    if (r < nRows) {
                        float* p = g_pool + bi0 * D + c;
                        asm volatile("red.global.add.v2.f32 [%0], {%1, %2};"
                                     :: "l"(p), "f"(v0), "f"(v1) : "memory");
                    }
                    if (r + 8 < nRows) {
                        float* p = g_pool + bi8 * D + c;
                        asm volatile("red.global.add.v2.f32 [%0], {%1, %2};"
                                     :: "l"(p), "f"(v2), "f"(v3) : "memory");
                    }
                } else {
                    if (r < nRows)
                        *(float2*)(out + (size_t)r * D + c) = make_float2(v0, v1);
                    if (r + 8 < nRows)
                        *(float2*)(out + (size_t)(r + 8) * D + c) = make_float2(v2, v3);
                }
            }
        }
    }
}

// ---------------- classifier ------------------------------------------------
__global__ void classifier_kernel(const int* __restrict__ batch, int nNodes,
                                  const float* __restrict__ w1,
                                  const float* __restrict__ b1,
                                  const float* __restrict__ w2,
                                  const float* __restrict__ b2,
                                  float* __restrict__ out) {
    __shared__ float gs[D];
    __shared__ float hs[64];
    __shared__ float cnt_s;
    const int b = blockIdx.x;
    const int t = threadIdx.x;

    if (t == 0) {
        int lo = 0, hi = nNodes;
        while (lo < hi) { int m = (lo + hi) >> 1; if (batch[m] < b) lo = m + 1; else hi = m; }
        int start = lo;
        lo = start; hi = nNodes;
        while (lo < hi) { int m = (lo + hi) >> 1; if (batch[m] <= b) lo = m + 1; else hi = m; }
        cnt_s = fmaxf((float)(lo - start), 1.0f);
    }
    __syncthreads();

    gs[t] = g_pool[b * D + t] / cnt_s;
    __syncthreads();

    if (t < 64) {
        float h = b1[t];
#pragma unroll 8
        for (int k = 0; k < D; ++k) h += gs[k] * w1[k * 64 + t];
        hs[t] = fmaxf(h, 0.f);
    }
    __syncthreads();

    if (t == 0) {
        float o0 = b2[0], o1 = b2[1];
#pragma unroll 8
        for (int j = 0; j < 64; ++j) {
            o0 += hs[j] * w2[2 * j];
            o1 += hs[j] * w2[2 * j + 1];
        }
        float m = fmaxf(o0, o1);
        float e0 = expf(o0 - m), e1 = expf(o1 - m);
        float s = e0 + e1;
        out[2 * b]     = e0 / s;
        out[2 * b + 1] = e1 / s;
    }
}

// ---------------------------------------------------------------------------
extern "C" void kernel_launch(void* const* d_in, const int* in_sizes, int n_in,
                              void* d_out, int out_size) {
    const int*   x_idx   = (const int*)d_in[0];
    const int*   edge    = (const int*)d_in[1];
    const int*   batch   = (const int*)d_in[2];
    const float* emb     = (const float*)d_in[3];
    const float* conv_w1 = (const float*)d_in[4];
    const float* conv_b1 = (const float*)d_in[5];
    const float* conv_w2 = (const float*)d_in[6];
    const float* conv_b2 = (const float*)d_in[7];
    const float* mlp_w1  = (const float*)d_in[8];
    const float* mlp_b1  = (const float*)d_in[9];
    const float* mlp_w2  = (const float*)d_in[10];
    const float* mlp_b2  = (const float*)d_in[11];
    float* out = (float*)d_out;

    const int nNodes = in_sizes[0];
    const int nEdges = in_sizes[1] / 2;
    const int nVocab = in_sizes[3] / D;
    const int* src = edge;
    const int* dst = edge + nEdges;

    float *px, *py, *pembT;
    cudaGetSymbolAddress((void**)&px,    g_x);
    cudaGetSymbolAddress((void**)&py,    g_y);
    cudaGetSymbolAddress((void**)&pembT, g_embT);

    const int smem_small = 4 * TILE_B;   // 139264
    const int smem_big   = 6 * TILE_B;   // 208896
    cudaFuncSetAttribute(mlp_mma<0>, cudaFuncAttributeMaxDynamicSharedMemorySize, smem_small);
    cudaFuncSetAttribute(mlp_mma<1>, cudaFuncAttributeMaxDynamicSharedMemorySize, smem_small);
    cudaFuncSetAttribute(mlp_mma<2>, cudaFuncAttributeMaxDynamicSharedMemorySize, smem_big);

    const int nodeTiles = (nNodes + TMG - 1) / TMG;    // 64-row tiles
    const int embTiles  = (nVocab + TMG - 1) / TMG;
    const int grid1 = (nodeTiles + 1) / 2 < 148 ? (nodeTiles + 1) / 2 : 148;
    const int gridE = (embTiles + 1) / 2 < 148 ? (embTiles + 1) / 2 : 148;
    const int nb = (nNodes + SCAN_BLK - 1) / SCAN_BLK;

    // CSR build + zeros + weight prep
    zero_kernel<<<256, 256>>>();
    prep_weights<<<(6 * D * D + 255) / 256, 256>>>(conv_w1, conv_w2);
    hist_kernel<<<(nEdges + 255) / 256, 256>>>(dst, nEdges);
    scanA_kernel<<<nb, SCAN_BLK>>>(nNodes);
    scanB_kernel<<<1, NB_MAX>>>(nb);
    scanC_kernel<<<nb, SCAN_BLK>>>(nNodes);
    fill_kernel<<<(nEdges + 255) / 256, 256>>>(src, dst, nEdges);

    // embT = emb @ conv_w1[0]
    mlp_mma<0><<<gridE, NT_MLP, smem_small>>>(emb, nullptr, -1, 0, nullptr, nullptr,
                                              pembT, nullptr, nVocab, embTiles);

    // layer 0 (fused gather + aggregate): embT[x_idx] pull -> px
    mlp_mma<1><<<grid1, NT_MLP, smem_small>>>(nullptr, x_idx, -1, 3, conv_b1, conv_b2,
                                              px, nullptr, nNodes, nodeTiles);

    // layer 1: px -> py
    mlp_mma<2><<<grid1, NT_MLP, smem_big>>>(px, nullptr, 1, 4, conv_b1 + D, conv_b2 + D,
                                            py, nullptr, nNodes, nodeTiles);

    // layer 2: py -> pooled sums
    mlp_mma<2><<<grid1, NT_MLP, smem_big>>>(py, nullptr, 2, 5, conv_b1 + 2 * D,
                                            conv_b2 + 2 * D, nullptr, batch,
                                            nNodes, nodeTiles);

    // classifier + softmax
    classifier_kernel<<<N_GRAPHS, D>>>(batch, nNodes, mlp_w1, mlp_b1, mlp_w2,
                                       mlp_b2, out);
}

// round 10
// speedup vs baseline: 1.8131x; 1.0051x over previous
#include <cuda_runtime.h>
#include <cuda_bf16.h>
#include <math.h>
#include <stdint.h>

// Problem constants
#define N_NODES   100000
#define N_EDGES   600000
#define N_GRAPHS  1000
#define VOCAB     10000
#define D         128
#define TMG       64               // rows per GROUP tile
#define ROWB      272              // padded smem row stride in bytes (136 bf16)
#define TILE_B    (128 * ROWB)     // full 128-row buffer (two 64-row group halves)
#define HALF_B    (64 * ROWB)
#define NT_MLP    512              // 16 warps: 2 groups x 8 warps
#define SCAN_BLK  1024
#define NB_MAX    128

// ---------------- scratch -------------------------------------------------
__device__ float g_x[N_NODES * D];
__device__ float g_y[N_NODES * D];
__device__ float g_embT[VOCAB * D];
__device__ float g_pool[N_GRAPHS * D];
__device__ int   g_cnt[N_NODES];
__device__ int   g_cur[N_NODES];
__device__ int   g_rowptr[N_NODES + 1];
__device__ int   g_adj[N_EDGES];
__device__ int   g_bsum[NB_MAX];
__device__ int   g_boff[NB_MAX];
// split-bf16 weights, transposed [n][k]; mats 0..2 = conv_w1[L], 3..5 = conv_w2[L]
__device__ __nv_bfloat16 g_wh[6][D * D];
__device__ __nv_bfloat16 g_wl[6][D * D];

// ---------------- helpers -------------------------------------------------
__device__ __forceinline__ uint32_t smem_u32(const void* p) {
    uint32_t a;
    asm("{ .reg .u64 t; cvta.to.shared.u64 t, %1; cvt.u32.u64 %0, t; }"
        : "=r"(a) : "l"(p));
    return a;
}

__device__ __forceinline__ uint32_t pack_bf16(float a, float b) {
    __nv_bfloat162 t;
    t.x = __float2bfloat16_rn(a);
    t.y = __float2bfloat16_rn(b);
    return *(uint32_t*)&t;
}

__device__ __forceinline__ void mma16816(float* d, uint32_t a0, uint32_t a1,
                                         uint32_t a2, uint32_t a3,
                                         uint32_t b0, uint32_t b1) {
    asm volatile(
        "mma.sync.aligned.m16n8k16.row.col.f32.bf16.bf16.f32 "
        "{%0,%1,%2,%3}, {%4,%5,%6,%7}, {%8,%9}, {%0,%1,%2,%3};\n"
        : "+f"(d[0]), "+f"(d[1]), "+f"(d[2]), "+f"(d[3])
        : "r"(a0), "r"(a1), "r"(a2), "r"(a3), "r"(b0), "r"(b1));
}

__device__ __forceinline__ void ldm_x4(uint32_t& r0, uint32_t& r1, uint32_t& r2,
                                       uint32_t& r3, uint32_t addr) {
    asm volatile("ldmatrix.sync.aligned.m8n8.x4.shared.b16 {%0,%1,%2,%3}, [%4];"
                 : "=r"(r0), "=r"(r1), "=r"(r2), "=r"(r3) : "r"(addr));
}

__device__ __forceinline__ void ldm_x2(uint32_t& r0, uint32_t& r1, uint32_t addr) {
    asm volatile("ldmatrix.sync.aligned.m8n8.x2.shared.b16 {%0,%1}, [%2];"
                 : "=r"(r0), "=r"(r1) : "r"(addr));
}

__device__ __forceinline__ void group_bar(int g) {
    asm volatile("bar.sync %0, %1;" :: "r"(g + 1), "r"(256) : "memory");
}

// ---------------- CSR build -------------------------------------------------
__global__ void zero_kernel() {
    int i = blockIdx.x * blockDim.x + threadIdx.x;
    int n = gridDim.x * blockDim.x;
    for (int j = i; j < N_NODES; j += n) g_cnt[j] = 0;
    for (int j = i; j < N_GRAPHS * D; j += n) g_pool[j] = 0.0f;
}

__global__ void hist_kernel(const int* __restrict__ dst, int nE) {
    int i = blockIdx.x * blockDim.x + threadIdx.x;
    if (i < nE) atomicAdd(&g_cnt[dst[i]], 1);
}

__global__ void __launch_bounds__(SCAN_BLK, 1) scanA_kernel(int nNodes) {
    __shared__ int red[SCAN_BLK];
    int i = blockIdx.x * SCAN_BLK + threadIdx.x;
    int v = (i < nNodes) ? g_cnt[i] : 0;
    red[threadIdx.x] = v;
    __syncthreads();
    for (int off = SCAN_BLK / 2; off > 0; off >>= 1) {
        if (threadIdx.x < off) red[threadIdx.x] += red[threadIdx.x + off];
        __syncthreads();
    }
    if (threadIdx.x == 0) g_bsum[blockIdx.x] = red[0];
}

__global__ void __launch_bounds__(NB_MAX, 1) scanB_kernel(int nb) {
    __shared__ int s[NB_MAX];
    int t = threadIdx.x;
    int v = (t < nb) ? g_bsum[t] : 0;
    s[t] = v;
    __syncthreads();
    for (int off = 1; off < NB_MAX; off <<= 1) {
        int u = (t >= off) ? s[t - off] : 0;
        __syncthreads();
        s[t] += u;
        __syncthreads();
    }
    if (t < nb) g_boff[t] = s[t] - v;
}

__global__ void __launch_bounds__(SCAN_BLK, 1) scanC_kernel(int nNodes) {
    __shared__ int s[SCAN_BLK];
    int i = blockIdx.x * SCAN_BLK + threadIdx.x;
    int t = threadIdx.x;
    int v = (i < nNodes) ? g_cnt[i] : 0;
    s[t] = v;
    __syncthreads();
    for (int off = 1; off < SCAN_BLK; off <<= 1) {
        int u = (t >= off) ? s[t - off] : 0;
        __syncthreads();
        s[t] += u;
        __syncthreads();
    }
    if (i < nNodes) {
        int excl = s[t] - v + g_boff[blockIdx.x];
        g_rowptr[i] = excl;
        g_cur[i] = excl;
        if (i == nNodes - 1) g_rowptr[nNodes] = excl + v;
    }
}

__global__ void fill_kernel(const int* __restrict__ src,
                            const int* __restrict__ dst, int nE) {
    int i = blockIdx.x * blockDim.x + threadIdx.x;
    if (i >= nE) return;
    int pos = atomicAdd(&g_cur[dst[i]], 1);
    g_adj[pos] = src[i];
}

// ---------------- weight prep -----------------------------------------------
__global__ void prep_weights(const float* __restrict__ w1,
                             const float* __restrict__ w2) {
    int i = blockIdx.x * blockDim.x + threadIdx.x;
    if (i >= 6 * D * D) return;
    int m = i / (D * D), kn = i % (D * D);
    int k = kn / D, n = kn % D;
    float v = (m < 3) ? w1[m * D * D + kn] : w2[(m - 3) * D * D + kn];
    __nv_bfloat16 h = __float2bfloat16_rn(v);
    __nv_bfloat16 l = __float2bfloat16_rn(v - __bfloat162float(h));
    g_wh[m][n * D + k] = h;
    g_wl[m][n * D + k] = l;
}

// ---------------- GEMM phase (per warp: 32x32 patch of a 64-row tile) -------
__device__ __forceinline__ void gemm_phase(uint32_t aH, uint32_t aL,
                                           uint32_t bH, uint32_t bL,
                                           float (&acc)[2][4][4]) {
#pragma unroll
    for (int k0 = 0; k0 < D; k0 += 16) {
        uint32_t ah0[2], ah1[2], ah2[2], ah3[2];
        uint32_t al0[2], al1[2], al2[2], al3[2];
        uint32_t bh0[4], bh1[4], bl0[4], bl1[4];
#pragma unroll
        for (int mt = 0; mt < 2; ++mt) {
            ldm_x4(ah0[mt], ah1[mt], ah2[mt], ah3[mt], aH + mt * (16 * ROWB) + k0 * 2);
            ldm_x4(al0[mt], al1[mt], al2[mt], al3[mt], aL + mt * (16 * ROWB) + k0 * 2);
        }
#pragma unroll
        for (int nt = 0; nt < 4; ++nt) {
            ldm_x2(bh0[nt], bh1[nt], bH + nt * (8 * ROWB) + k0 * 2);
            ldm_x2(bl0[nt], bl1[nt], bL + nt * (8 * ROWB) + k0 * 2);
        }
#pragma unroll
        for (int mt = 0; mt < 2; ++mt) {
#pragma unroll
            for (int nt = 0; nt < 4; ++nt) {
                mma16816(acc[mt][nt], ah0[mt], ah1[mt], ah2[mt], ah3[mt], bh0[nt], bh1[nt]);
                mma16816(acc[mt][nt], ah0[mt], ah1[mt], ah2[mt], ah3[mt], bl0[nt], bl1[nt]);
                mma16816(acc[mt][nt], al0[mt], al1[mt], al2[mt], al3[mt], bh0[nt], bh1[nt]);
            }
        }
    }
}

// ---- batched CSR gather: agg = base + sum_{j in [e0,e1)} rows[idx(j)] ------
// 4-wide independent loads (MLP=4) + predicated 3-way remainder.
__device__ __forceinline__ float4 gather_sum(const float* __restrict__ rows,
                                             const int* __restrict__ xidx,
                                             int e0, int e1, int c4, float4 v) {
    int j = e0;
    for (; j + 4 <= e1; j += 4) {
        int n0 = g_adj[j], n1 = g_adj[j + 1], n2 = g_adj[j + 2], n3 = g_adj[j + 3];
        if (xidx) { n0 = xidx[n0]; n1 = xidx[n1]; n2 = xidx[n2]; n3 = xidx[n3]; }
        float4 u0 = *(const float4*)(rows + (size_t)n0 * D + c4);
        float4 u1 = *(const float4*)(rows + (size_t)n1 * D + c4);
        float4 u2 = *(const float4*)(rows + (size_t)n2 * D + c4);
        float4 u3 = *(const float4*)(rows + (size_t)n3 * D + c4);
        v.x += u0.x + u1.x + u2.x + u3.x;
        v.y += u0.y + u1.y + u2.y + u3.y;
        v.z += u0.z + u1.z + u2.z + u3.z;
        v.w += u0.w + u1.w + u2.w + u3.w;
    }
    int rem = e1 - j;
    float4 u0, u1, u2;
    if (rem > 0) {
        int n0 = g_adj[j];
        if (xidx) n0 = xidx[n0];
        u0 = *(const float4*)(rows + (size_t)n0 * D + c4);
    }
    if (rem > 1) {
        int n1 = g_adj[j + 1];
        if (xidx) n1 = xidx[n1];
        u1 = *(const float4*)(rows + (size_t)n1 * D + c4);
    }
    if (rem > 2) {
        int n2 = g_adj[j + 2];
        if (xidx) n2 = xidx[n2];
        u2 = *(const float4*)(rows + (size_t)n2 * D + c4);
    }
    if (rem > 0) { v.x += u0.x; v.y += u0.y; v.z += u0.z; v.w += u0.w; }
    if (rem > 1) { v.x += u1.x; v.y += u1.y; v.z += u1.z; v.w += u1.w; }
    if (rem > 2) { v.x += u2.x; v.y += u2.y; v.z += u2.z; v.w += u2.w; }
    return v;
}

// ---------------- persistent fused aggregate+MLP, 2 groups per CTA ----------
// MODE 0: out = x @ W[w2_id]
// MODE 1: A = sum embT[x_idx[self+nbrs]]; h = relu(A + b1); out = relu(h@W2 + b2)
// MODE 2: A = x[self] + sum x[nbrs]; h = relu(A@W1 + b1); out = relu(h@W2 + b2)
// pbatch != nullptr: red.add result into g_pool[batch[row]] instead of out.
template <int MODE>
__global__ void __launch_bounds__(NT_MLP, 1)
mlp_mma(const float* __restrict__ x, const int* __restrict__ xidx,
        int w1_id, int w2_id,
        const float* __restrict__ b1, const float* __restrict__ b2,
        float* __restrict__ out, const int* __restrict__ pbatch,
        int nRows, int nTiles) {
    extern __shared__ __align__(16) unsigned char sm[];
    unsigned char* Ah  = sm;                 // 128 rows: group g owns rows [64g, 64g+64)
    unsigned char* Al  = sm + TILE_B;
    unsigned char* W2h = sm + 2 * TILE_B;
    unsigned char* W2l = sm + 3 * TILE_B;
    unsigned char* W1h = sm + 4 * TILE_B;    // MODE 2 only
    unsigned char* W1l = sm + 5 * TILE_B;
    __shared__ float b1s[D], b2s[D];

    const int tid  = threadIdx.x;
    const int lane = tid & 31, wid = tid >> 5;
    const int g    = wid >> 3;               // group 0 / 1
    const int wg   = wid & 7;                // warp within group
    const int R0 = (wg >> 2) * 32, N0 = (wg & 3) * 32;

    if (MODE != 0 && tid < D) {
        b2s[tid] = b2[tid];
        if (MODE == 2) b1s[tid] = b1[tid];
    }

    // stage weights once (all 16 warps)
    {
        const uint4* s2h = (const uint4*)g_wh[w2_id];
        const uint4* s2l = (const uint4*)g_wl[w2_id];
        for (int i = tid; i < 128 * 16; i += NT_MLP) {
            int n = i >> 4, c = i & 15;
            *(uint4*)(W2h + n * ROWB + c * 16) = s2h[n * 16 + c];
            *(uint4*)(W2l + n * ROWB + c * 16) = s2l[n * 16 + c];
        }
        if (MODE == 2) {
            const uint4* s1h = (const uint4*)g_wh[w1_id];
            const uint4* s1l = (const uint4*)g_wl[w1_id];
            for (int i = tid; i < 128 * 16; i += NT_MLP) {
                int n = i >> 4, c = i & 15;
                *(uint4*)(W1h + n * ROWB + c * 16) = s1h[n * 16 + c];
                *(uint4*)(W1l + n * ROWB + c * 16) = s1l[n * 16 + c];
            }
        }
    }
    __syncthreads();     // weights visible to both groups; last full-CTA barrier

    // group-local A-half base and per-lane addresses
    unsigned char* AhG = Ah + g * HALF_B;
    unsigned char* AlG = Al + g * HALF_B;
    const uint32_t aOff = (uint32_t)(R0 + (lane & 15)) * ROWB + ((lane >> 4) * 16);
    const uint32_t bOff = (uint32_t)(N0 + (lane & 7)) * ROWB + (((lane >> 3) & 1) * 16);
    const uint32_t aH = smem_u32(AhG) + aOff, aL = smem_u32(AlG) + aOff;
    const uint32_t w2H = smem_u32(W2h) + bOff, w2L = smem_u32(W2l) + bOff;
    const uint32_t w1H = (MODE == 2) ? smem_u32(W1h) + bOff : 0;
    const uint32_t w1L = (MODE == 2) ? smem_u32(W1l) + bOff : 0;

    for (int t = blockIdx.x * 2 + g; t < nTiles; t += gridDim.x * 2) {
        const int row0 = t * TMG;
        group_bar(g);   // protect this group's A half from previous iteration

        // ---- fused aggregate + split-convert A half (warp per row) ----
        for (int rr = wg; rr < TMG; rr += 8) {
            const int gr = row0 + rr;
            float4 v = make_float4(0.f, 0.f, 0.f, 0.f);
            if (gr < nRows) {
                const int c4 = lane * 4;
                if (MODE == 0) {
                    v = *(const float4*)(x + (size_t)gr * D + c4);
                } else if (MODE == 1) {
                    int self = xidx[gr];
                    int e0 = g_rowptr[gr], e1 = g_rowptr[gr + 1];
                    v = *(const float4*)(g_embT + (size_t)self * D + c4);
                    v = gather_sum(g_embT, xidx, e0, e1, c4, v);
                    float4 bv = *(const float4*)(b1 + c4);
                    v.x = fmaxf(v.x + bv.x, 0.f); v.y = fmaxf(v.y + bv.y, 0.f);
                    v.z = fmaxf(v.z + bv.z, 0.f); v.w = fmaxf(v.w + bv.w, 0.f);
                } else {
                    int e0 = g_rowptr[gr], e1 = g_rowptr[gr + 1];
                    v = *(const float4*)(x + (size_t)gr * D + c4);
                    v = gather_sum(x, nullptr, e0, e1, c4, v);
                }
            }
            uint32_t h01 = pack_bf16(v.x, v.y), h23 = pack_bf16(v.z, v.w);
            float f0 = __uint_as_float(h01 << 16);
            float f1 = __uint_as_float(h01 & 0xffff0000u);
            float f2 = __uint_as_float(h23 << 16);
            float f3 = __uint_as_float(h23 & 0xffff0000u);
            *(uint2*)(AhG + rr * ROWB + lane * 8) = make_uint2(h01, h23);
            *(uint2*)(AlG + rr * ROWB + lane * 8) =
                make_uint2(pack_bf16(v.x - f0, v.y - f1), pack_bf16(v.z - f2, v.w - f3));
        }
        group_bar(g);

        float acc[2][4][4];

        if (MODE == 2) {
            // phase 1: h = relu(A @ W1 + b1) -> back into AhG/AlG
#pragma unroll
            for (int nt = 0; nt < 4; ++nt) {
                int c = N0 + nt * 8 + (lane & 3) * 2;
                float bb0 = b1s[c], bb1 = b1s[c + 1];
#pragma unroll
                for (int mt = 0; mt < 2; ++mt) {
                    acc[mt][nt][0] = bb0; acc[mt][nt][1] = bb1;
                    acc[mt][nt][2] = bb0; acc[mt][nt][3] = bb1;
                }
            }
            gemm_phase(aH, aL, w1H, w1L, acc);
            group_bar(g);
#pragma unroll
            for (int mt = 0; mt < 2; ++mt) {
#pragma unroll
                for (int nt = 0; nt < 4; ++nt) {
                    int r = R0 + mt * 16 + (lane >> 2);
                    int c = N0 + nt * 8 + (lane & 3) * 2;
                    float v0 = fmaxf(acc[mt][nt][0], 0.f), v1 = fmaxf(acc[mt][nt][1], 0.f);
                    float v2 = fmaxf(acc[mt][nt][2], 0.f), v3 = fmaxf(acc[mt][nt][3], 0.f);
                    uint32_t h01 = pack_bf16(v0, v1), h23 = pack_bf16(v2, v3);
                    float f0 = __uint_as_float(h01 << 16);
                    float f1 = __uint_as_float(h01 & 0xffff0000u);
                    float f2 = __uint_as_float(h23 << 16);
                    float f3 = __uint_as_float(h23 & 0xffff0000u);
                    *(uint32_t*)(AhG + r * ROWB + c * 2)       = h01;
                    *(uint32_t*)(AhG + (r + 8) * ROWB + c * 2) = h23;
                    *(uint32_t*)(AlG + r * ROWB + c * 2)       = pack_bf16(v0 - f0, v1 - f1);
                    *(uint32_t*)(AlG + (r + 8) * ROWB + c * 2) = pack_bf16(v2 - f2, v3 - f3);
                }
            }
            group_bar(g);
        }

        // phase 2
        if (MODE == 0) {
#pragma unroll
            for (int mt = 0; mt < 2; ++mt)
#pragma unroll
                for (int nt = 0; nt < 4; ++nt)
                    acc[mt][nt][0] = acc[mt][nt][1] = acc[mt][nt][2] = acc[mt][nt][3] = 0.f;
        } else {
#pragma unroll
            for (int nt = 0; nt < 4; ++nt) {
                int c = N0 + nt * 8 + (lane & 3) * 2;
                float bb0 = b2s[c], bb1 = b2s[c + 1];
#pragma unroll
                for (int mt = 0; mt < 2; ++mt) {
                    acc[mt][nt][0] = bb0; acc[mt][nt][1] = bb1;
                    acc[mt][nt][2] = bb0; acc[mt][nt][3] = bb1;
                }
            }
        }
        gemm_phase(aH, aL, w2H, w2L, acc);

        // ---- epilogue ----
#pragma unroll
        for (int mt = 0; mt < 2; ++mt) {
            int r = row0 + R0 + mt * 16 + (lane >> 2);
            int bi0 = 0, bi8 = 0;
            if (pbatch) {
                if (r < nRows)     bi0 = pbatch[r];
                if (r + 8 < nRows) bi8 = pbatch[r + 8];
            }
#pragma unroll
            for (int nt = 0; nt < 4; ++nt) {
                int c = N0 + nt * 8 + (lane & 3) * 2;
                float v0 = acc[mt][nt][0], v1 = acc[mt][nt][1];
                float v2 = acc[mt][nt][2], v3 = acc[mt][nt][3];
                if (MODE != 0) {
                    v0 = fmaxf(v0, 0.f); v1 = fmaxf(v1, 0.f);
                    v2 = fmaxf(v2, 0.f); v3 = fmaxf(v3, 0.f);
                }
                if (pbatch) {
                    if (r < nRows) {
                        float* p = g_pool + bi0 * D + c;
                        asm volatile("red.global.add.v2.f32 [%0], {%1, %2};"
                                     :: "l"(p), "f"(v0), "f"(v1) : "memory");
                    }
                    if (r + 8 < nRows) {
                        float* p = g_pool + bi8 * D + c;
                        asm volatile("red.global.add.v2.f32 [%0], {%1, %2};"
                                     :: "l"(p), "f"(v2), "f"(v3) : "memory");
                    }
                } else {
                    if (r < nRows)
                        *(float2*)(out + (size_t)r * D + c) = make_float2(v0, v1);
                    if (r + 8 < nRows)
                        *(float2*)(out + (size_t)(r + 8) * D + c) = make_float2(v2, v3);
                }
            }
        }
    }
}

// ---------------- classifier ------------------------------------------------
__global__ void classifier_kernel(const int* __restrict__ batch, int nNodes,
                                  const float* __restrict__ w1,
                                  const float* __restrict__ b1,
                                  const float* __restrict__ w2,
                                  const float* __restrict__ b2,
                                  float* __restrict__ out) {
    __shared__ float gs[D];
    __shared__ float hs[64];
    __shared__ float cnt_s;
    const int b = blockIdx.x;
    const int t = threadIdx.x;

    if (t == 0) {
        int lo = 0, hi = nNodes;
        while (lo < hi) { int m = (lo + hi) >> 1; if (batch[m] < b) lo = m + 1; else hi = m; }
        int start = lo;
        lo = start; hi = nNodes;
        while (lo < hi) { int m = (lo + hi) >> 1; if (batch[m] <= b) lo = m + 1; else hi = m; }
        cnt_s = fmaxf((float)(lo - start), 1.0f);
    }
    __syncthreads();

    gs[t] = g_pool[b * D + t] / cnt_s;
    __syncthreads();

    if (t < 64) {
        float h = b1[t];
#pragma unroll 8
        for (int k = 0; k < D; ++k) h += gs[k] * w1[k * 64 + t];
        hs[t] = fmaxf(h, 0.f);
    }
    __syncthreads();

    if (t == 0) {
        float o0 = b2[0], o1 = b2[1];
#pragma unroll 8
        for (int j = 0; j < 64; ++j) {
            o0 += hs[j] * w2[2 * j];
            o1 += hs[j] * w2[2 * j + 1];
        }
        float m = fmaxf(o0, o1);
        float e0 = expf(o0 - m), e1 = expf(o1 - m);
        float s = e0 + e1;
        out[2 * b]     = e0 / s;
        out[2 * b + 1] = e1 / s;
    }
}

// ---------------------------------------------------------------------------
extern "C" void kernel_launch(void* const* d_in, const int* in_sizes, int n_in,
                              void* d_out, int out_size) {
    const int*   x_idx   = (const int*)d_in[0];
    const int*   edge    = (const int*)d_in[1];
    const int*   batch   = (const int*)d_in[2];
    const float* emb     = (const float*)d_in[3];
    const float* conv_w1 = (const float*)d_in[4];
    const float* conv_b1 = (const float*)d_in[5];
    const float* conv_w2 = (const float*)d_in[6];
    const float* conv_b2 = (const float*)d_in[7];
    const float* mlp_w1  = (const float*)d_in[8];
    const float* mlp_b1  = (const float*)d_in[9];
    const float* mlp_w2  = (const float*)d_in[10];
    const float* mlp_b2  = (const float*)d_in[11];
    float* out = (float*)d_out;

    const int nNodes = in_sizes[0];
    const int nEdges = in_sizes[1] / 2;
    const int nVocab = in_sizes[3] / D;
    const int* src = edge;
    const int* dst = edge + nEdges;

    float *px, *py, *pembT;
    cudaGetSymbolAddress((void**)&px,    g_x);
    cudaGetSymbolAddress((void**)&py,    g_y);
    cudaGetSymbolAddress((void**)&pembT, g_embT);

    const int smem_small = 4 * TILE_B;   // 139264
    const int smem_big   = 6 * TILE_B;   // 208896
    cudaFuncSetAttribute(mlp_mma<0>, cudaFuncAttributeMaxDynamicSharedMemorySize, smem_small);
    cudaFuncSetAttribute(mlp_mma<1>, cudaFuncAttributeMaxDynamicSharedMemorySize, smem_small);
    cudaFuncSetAttribute(mlp_mma<2>, cudaFuncAttributeMaxDynamicSharedMemorySize, smem_big);

    const int nodeTiles = (nNodes + TMG - 1) / TMG;    // 64-row tiles
    const int embTiles  = (nVocab + TMG - 1) / TMG;
    const int grid1 = (nodeTiles + 1) / 2 < 148 ? (nodeTiles + 1) / 2 : 148;
    const int gridE = (embTiles + 1) / 2 < 148 ? (embTiles + 1) / 2 : 148;
    const int nb = (nNodes + SCAN_BLK - 1) / SCAN_BLK;

    // CSR build + zeros + weight prep
    zero_kernel<<<256, 256>>>();
    prep_weights<<<(6 * D * D + 255) / 256, 256>>>(conv_w1, conv_w2);
    hist_kernel<<<(nEdges + 255) / 256, 256>>>(dst, nEdges);
    scanA_kernel<<<nb, SCAN_BLK>>>(nNodes);
    scanB_kernel<<<1, NB_MAX>>>(nb);
    scanC_kernel<<<nb, SCAN_BLK>>>(nNodes);
    fill_kernel<<<(nEdges + 255) / 256, 256>>>(src, dst, nEdges);

    // embT = emb @ conv_w1[0]
    mlp_mma<0><<<gridE, NT_MLP, smem_small>>>(emb, nullptr, -1, 0, nullptr, nullptr,
                                              pembT, nullptr, nVocab, embTiles);

    // layer 0 (fused gather + aggregate): embT[x_idx] pull -> px
    mlp_mma<1><<<grid1, NT_MLP, smem_small>>>(nullptr, x_idx, -1, 3, conv_b1, conv_b2,
                                              px, nullptr, nNodes, nodeTiles);

    // layer 1: px -> py
    mlp_mma<2><<<grid1, NT_MLP, smem_big>>>(px, nullptr, 1, 4, conv_b1 + D, conv_b2 + D,
                                            py, nullptr, nNodes, nodeTiles);

    // layer 2: py -> pooled sums
    mlp_mma<2><<<grid1, NT_MLP, smem_big>>>(py, nullptr, 2, 5, conv_b1 + 2 * D,
                                            conv_b2 + 2 * D, nullptr, batch,
                                            nNodes, nodeTiles);

    // classifier + softmax
    classifier_kernel<<<N_GRAPHS, D>>>(batch, nNodes, mlp_w1, mlp_b1, mlp_w2,
                                       mlp_b2, out);
}

// round 12
// speedup vs baseline: 1.8314x; 1.0101x over previous
#include <cuda_runtime.h>
#include <cuda_bf16.h>
#include <math.h>
#include <stdint.h>

// Problem constants
#define N_NODES   100000
#define N_EDGES   600000
#define N_GRAPHS  1000
#define VOCAB     10000
#define D         128
#define TMG       32               // rows per GROUP tile
#define NGROUP    4                // groups per CTA
#define GW        4                // warps per group
#define ROWB      272              // padded smem row stride in bytes (136 bf16)
#define TILE_B    (128 * ROWB)     // full 128-row buffer (four 32-row group quarters)
#define QUART_B   (32 * ROWB)
#define NT_MLP    512              // 16 warps: 4 groups x 4 warps
#define SCAN_BLK  1024
#define NB_MAX    128

// ---------------- scratch -------------------------------------------------
__device__ float g_x[N_NODES * D];
__device__ float g_y[N_NODES * D];
__device__ float g_embT[VOCAB * D];
__device__ float g_pool[N_GRAPHS * D];
__device__ int   g_cnt[N_NODES];
__device__ int   g_cur[N_NODES];
__device__ int   g_rowptr[N_NODES + 1];
__device__ int   g_adj[N_EDGES];
__device__ int   g_bsum[NB_MAX];
__device__ int   g_boff[NB_MAX];
// split-bf16 weights, transposed [n][k]; mats 0..2 = conv_w1[L], 3..5 = conv_w2[L]
__device__ __nv_bfloat16 g_wh[6][D * D];
__device__ __nv_bfloat16 g_wl[6][D * D];

// ---------------- helpers -------------------------------------------------
__device__ __forceinline__ uint32_t smem_u32(const void* p) {
    uint32_t a;
    asm("{ .reg .u64 t; cvta.to.shared.u64 t, %1; cvt.u32.u64 %0, t; }"
        : "=r"(a) : "l"(p));
    return a;
}

__device__ __forceinline__ uint32_t pack_bf16(float a, float b) {
    __nv_bfloat162 t;
    t.x = __float2bfloat16_rn(a);
    t.y = __float2bfloat16_rn(b);
    return *(uint32_t*)&t;
}

__device__ __forceinline__ void mma16816(float* d, uint32_t a0, uint32_t a1,
                                         uint32_t a2, uint32_t a3,
                                         uint32_t b0, uint32_t b1) {
    asm volatile(
        "mma.sync.aligned.m16n8k16.row.col.f32.bf16.bf16.f32 "
        "{%0,%1,%2,%3}, {%4,%5,%6,%7}, {%8,%9}, {%0,%1,%2,%3};\n"
        : "+f"(d[0]), "+f"(d[1]), "+f"(d[2]), "+f"(d[3])
        : "r"(a0), "r"(a1), "r"(a2), "r"(a3), "r"(b0), "r"(b1));
}

__device__ __forceinline__ void ldm_x4(uint32_t& r0, uint32_t& r1, uint32_t& r2,
                                       uint32_t& r3, uint32_t addr) {
    asm volatile("ldmatrix.sync.aligned.m8n8.x4.shared.b16 {%0,%1,%2,%3}, [%4];"
                 : "=r"(r0), "=r"(r1), "=r"(r2), "=r"(r3) : "r"(addr));
}

__device__ __forceinline__ void ldm_x2(uint32_t& r0, uint32_t& r1, uint32_t addr) {
    asm volatile("ldmatrix.sync.aligned.m8n8.x2.shared.b16 {%0,%1}, [%2];"
                 : "=r"(r0), "=r"(r1) : "r"(addr));
}

__device__ __forceinline__ void group_bar(int g) {
    asm volatile("bar.sync %0, %1;" :: "r"(g + 1), "r"(GW * 32) : "memory");
}

// ---------------- CSR build -------------------------------------------------
__global__ void zero_kernel() {
    int i = blockIdx.x * blockDim.x + threadIdx.x;
    int n = gridDim.x * blockDim.x;
    for (int j = i; j < N_NODES; j += n) g_cnt[j] = 0;
    for (int j = i; j < N_GRAPHS * D; j += n) g_pool[j] = 0.0f;
}

__global__ void hist_kernel(const int* __restrict__ dst, int nE) {
    int i = blockIdx.x * blockDim.x + threadIdx.x;
    if (i < nE) atomicAdd(&g_cnt[dst[i]], 1);
}

__global__ void __launch_bounds__(SCAN_BLK, 1) scanA_kernel(int nNodes) {
    __shared__ int red[SCAN_BLK];
    int i = blockIdx.x * SCAN_BLK + threadIdx.x;
    int v = (i < nNodes) ? g_cnt[i] : 0;
    red[threadIdx.x] = v;
    __syncthreads();
    for (int off = SCAN_BLK / 2; off > 0; off >>= 1) {
        if (threadIdx.x < off) red[threadIdx.x] += red[threadIdx.x + off];
        __syncthreads();
    }
    if (threadIdx.x == 0) g_bsum[blockIdx.x] = red[0];
}

__global__ void __launch_bounds__(NB_MAX, 1) scanB_kernel(int nb) {
    __shared__ int s[NB_MAX];
    int t = threadIdx.x;
    int v = (t < nb) ? g_bsum[t] : 0;
    s[t] = v;
    __syncthreads();
    for (int off = 1; off < NB_MAX; off <<= 1) {
        int u = (t >= off) ? s[t - off] : 0;
        __syncthreads();
        s[t] += u;
        __syncthreads();
    }
    if (t < nb) g_boff[t] = s[t] - v;
}

__global__ void __launch_bounds__(SCAN_BLK, 1) scanC_kernel(int nNodes) {
    __shared__ int s[SCAN_BLK];
    int i = blockIdx.x * SCAN_BLK + threadIdx.x;
    int t = threadIdx.x;
    int v = (i < nNodes) ? g_cnt[i] : 0;
    s[t] = v;
    __syncthreads();
    for (int off = 1; off < SCAN_BLK; off <<= 1) {
        int u = (t >= off) ? s[t - off] : 0;
        __syncthreads();
        s[t] += u;
        __syncthreads();
    }
    if (i < nNodes) {
        int excl = s[t] - v + g_boff[blockIdx.x];
        g_rowptr[i] = excl;
        g_cur[i] = excl;
        if (i == nNodes - 1) g_rowptr[nNodes] = excl + v;
    }
}

__global__ void fill_kernel(const int* __restrict__ src,
                            const int* __restrict__ dst, int nE) {
    int i = blockIdx.x * blockDim.x + threadIdx.x;
    if (i >= nE) return;
    int pos = atomicAdd(&g_cur[dst[i]], 1);
    g_adj[pos] = src[i];
}

// ---------------- weight prep -----------------------------------------------
__global__ void prep_weights(const float* __restrict__ w1,
                             const float* __restrict__ w2) {
    int i = blockIdx.x * blockDim.x + threadIdx.x;
    if (i >= 6 * D * D) return;
    int m = i / (D * D), kn = i % (D * D);
    int k = kn / D, n = kn % D;
    float v = (m < 3) ? w1[m * D * D + kn] : w2[(m - 3) * D * D + kn];
    __nv_bfloat16 h = __float2bfloat16_rn(v);
    __nv_bfloat16 l = __float2bfloat16_rn(v - __bfloat162float(h));
    g_wh[m][n * D + k] = h;
    g_wl[m][n * D + k] = l;
}

// ---------------- GEMM phase (per warp: 32x32 patch of a 32-row tile) -------
__device__ __forceinline__ void gemm_phase(uint32_t aH, uint32_t aL,
                                           uint32_t bH, uint32_t bL,
                                           float (&acc)[2][4][4]) {
#pragma unroll
    for (int k0 = 0; k0 < D; k0 += 16) {
        uint32_t ah0[2], ah1[2], ah2[2], ah3[2];
        uint32_t al0[2], al1[2], al2[2], al3[2];
        uint32_t bh0[4], bh1[4], bl0[4], bl1[4];
#pragma unroll
        for (int mt = 0; mt < 2; ++mt) {
            ldm_x4(ah0[mt], ah1[mt], ah2[mt], ah3[mt], aH + mt * (16 * ROWB) + k0 * 2);
            ldm_x4(al0[mt], al1[mt], al2[mt], al3[mt], aL + mt * (16 * ROWB) + k0 * 2);
        }
#pragma unroll
        for (int nt = 0; nt < 4; ++nt) {
            ldm_x2(bh0[nt], bh1[nt], bH + nt * (8 * ROWB) + k0 * 2);
            ldm_x2(bl0[nt], bl1[nt], bL + nt * (8 * ROWB) + k0 * 2);
        }
#pragma unroll
        for (int mt = 0; mt < 2; ++mt) {
#pragma unroll
            for (int nt = 0; nt < 4; ++nt) {
                mma16816(acc[mt][nt], ah0[mt], ah1[mt], ah2[mt], ah3[mt], bh0[nt], bh1[nt]);
                mma16816(acc[mt][nt], ah0[mt], ah1[mt], ah2[mt], ah3[mt], bl0[nt], bl1[nt]);
                mma16816(acc[mt][nt], al0[mt], al1[mt], al2[mt], al3[mt], bh0[nt], bh1[nt]);
            }
        }
    }
}

// ---- batched CSR gather: agg = base + sum_{j in [e0,e1)} rows[idx(j)] ------
__device__ __forceinline__ float4 gather_sum(const float* __restrict__ rows,
                                             const int* __restrict__ xidx,
                                             int e0, int e1, int c4, float4 v) {
    int j = e0;
    for (; j + 4 <= e1; j += 4) {
        int n0 = g_adj[j], n1 = g_adj[j + 1], n2 = g_adj[j + 2], n3 = g_adj[j + 3];
        if (xidx) { n0 = xidx[n0]; n1 = xidx[n1]; n2 = xidx[n2]; n3 = xidx[n3]; }
        float4 u0 = *(const float4*)(rows + (size_t)n0 * D + c4);
        float4 u1 = *(const float4*)(rows + (size_t)n1 * D + c4);
        float4 u2 = *(const float4*)(rows + (size_t)n2 * D + c4);
        float4 u3 = *(const float4*)(rows + (size_t)n3 * D + c4);
        v.x += u0.x + u1.x + u2.x + u3.x;
        v.y += u0.y + u1.y + u2.y + u3.y;
        v.z += u0.z + u1.z + u2.z + u3.z;
        v.w += u0.w + u1.w + u2.w + u3.w;
    }
    int rem = e1 - j;
    float4 u0, u1, u2;
    if (rem > 0) {
        int n0 = g_adj[j];
        if (xidx) n0 = xidx[n0];
        u0 = *(const float4*)(rows + (size_t)n0 * D + c4);
    }
    if (rem > 1) {
        int n1 = g_adj[j + 1];
        if (xidx) n1 = xidx[n1];
        u1 = *(const float4*)(rows + (size_t)n1 * D + c4);
    }
    if (rem > 2) {
        int n2 = g_adj[j + 2];
        if (xidx) n2 = xidx[n2];
        u2 = *(const float4*)(rows + (size_t)n2 * D + c4);
    }
    if (rem > 0) { v.x += u0.x; v.y += u0.y; v.z += u0.z; v.w += u0.w; }
    if (rem > 1) { v.x += u1.x; v.y += u1.y; v.z += u1.z; v.w += u1.w; }
    if (rem > 2) { v.x += u2.x; v.y += u2.y; v.z += u2.z; v.w += u2.w; }
    return v;
}

// ---------------- persistent fused aggregate+MLP, 4 groups per CTA ----------
// MODE 0: out = x @ W[w2_id]
// MODE 1: A = sum embT[x_idx[self+nbrs]]; h = relu(A + b1); out = relu(h@W2 + b2)
// MODE 2: A = x[self] + sum x[nbrs]; h = relu(A@W1 + b1); out = relu(h@W2 + b2)
// pbatch != nullptr: red.add result into g_pool[batch[row]] instead of out.
template <int MODE>
__global__ void __launch_bounds__(NT_MLP, 1)
mlp_mma(const float* __restrict__ x, const int* __restrict__ xidx,
        int w1_id, int w2_id,
        const float* __restrict__ b1, const float* __restrict__ b2,
        float* __restrict__ out, const int* __restrict__ pbatch,
        int nRows, int nTiles) {
    extern __shared__ __align__(16) unsigned char sm[];
    unsigned char* Ah  = sm;                 // 128 rows: group g owns rows [32g, 32g+32)
    unsigned char* Al  = sm + TILE_B;
    unsigned char* W2h = sm + 2 * TILE_B;
    unsigned char* W2l = sm + 3 * TILE_B;
    unsigned char* W1h = sm + 4 * TILE_B;    // MODE 2 only
    unsigned char* W1l = sm + 5 * TILE_B;
    __shared__ float b1s[D], b2s[D];

    const int tid  = threadIdx.x;
    const int lane = tid & 31, wid = tid >> 5;
    const int g    = wid >> 2;               // group 0..3
    const int wg   = wid & 3;                // warp within group
    const int N0 = wg * 32;                  // each warp: rows 0..31 x cols N0..N0+31

    if (MODE != 0 && tid < D) {
        b2s[tid] = b2[tid];
        if (MODE == 2) b1s[tid] = b1[tid];
    }

    // stage weights once (all 16 warps)
    {
        const uint4* s2h = (const uint4*)g_wh[w2_id];
        const uint4* s2l = (const uint4*)g_wl[w2_id];
        for (int i = tid; i < 128 * 16; i += NT_MLP) {
            int n = i >> 4, c = i & 15;
            *(uint4*)(W2h + n * ROWB + c * 16) = s2h[n * 16 + c];
            *(uint4*)(W2l + n * ROWB + c * 16) = s2l[n * 16 + c];
        }
        if (MODE == 2) {
            const uint4* s1h = (const uint4*)g_wh[w1_id];
            const uint4* s1l = (const uint4*)g_wl[w1_id];
            for (int i = tid; i < 128 * 16; i += NT_MLP) {
                int n = i >> 4, c = i & 15;
                *(uint4*)(W1h + n * ROWB + c * 16) = s1h[n * 16 + c];
                *(uint4*)(W1l + n * ROWB + c * 16) = s1l[n * 16 + c];
            }
        }
    }
    __syncthreads();     // weights visible to all groups; last full-CTA barrier

    // group-local A-quarter base and per-lane addresses
    unsigned char* AhG = Ah + g * QUART_B;
    unsigned char* AlG = Al + g * QUART_B;
    const uint32_t aOff = (uint32_t)(lane & 15) * ROWB + ((lane >> 4) * 16);
    const uint32_t bOff = (uint32_t)(N0 + (lane & 7)) * ROWB + (((lane >> 3) & 1) * 16);
    const uint32_t aH = smem_u32(AhG) + aOff, aL = smem_u32(AlG) + aOff;
    const uint32_t w2H = smem_u32(W2h) + bOff, w2L = smem_u32(W2l) + bOff;
    const uint32_t w1H = (MODE == 2) ? smem_u32(W1h) + bOff : 0;
    const uint32_t w1L = (MODE == 2) ? smem_u32(W1l) + bOff : 0;

    for (int t = blockIdx.x * NGROUP + g; t < nTiles; t += gridDim.x * NGROUP) {
        const int row0 = t * TMG;
        group_bar(g);   // protect this group's A quarter from previous iteration

        // ---- fused aggregate + split-convert A quarter (warp per row) ----
        for (int rr = wg; rr < TMG; rr += GW) {
            const int gr = row0 + rr;
            float4 v = make_float4(0.f, 0.f, 0.f, 0.f);
            if (gr < nRows) {
                const int c4 = lane * 4;
                if (MODE == 0) {
                    v = *(const float4*)(x + (size_t)gr * D + c4);
                } else if (MODE == 1) {
                    int self = xidx[gr];
                    int e0 = g_rowptr[gr], e1 = g_rowptr[gr + 1];
                    v = *(const float4*)(g_embT + (size_t)self * D + c4);
                    v = gather_sum(g_embT, xidx, e0, e1, c4, v);
                    float4 bv = *(const float4*)(b1 + c4);
                    v.x = fmaxf(v.x + bv.x, 0.f); v.y = fmaxf(v.y + bv.y, 0.f);
                    v.z = fmaxf(v.z + bv.z, 0.f); v.w = fmaxf(v.w + bv.w, 0.f);
                } else {
                    int e0 = g_rowptr[gr], e1 = g_rowptr[gr + 1];
                    v = *(const float4*)(x + (size_t)gr * D + c4);
                    v = gather_sum(x, nullptr, e0, e1, c4, v);
                }
            }
            uint32_t h01 = pack_bf16(v.x, v.y), h23 = pack_bf16(v.z, v.w);
            float f0 = __uint_as_float(h01 << 16);
            float f1 = __uint_as_float(h01 & 0xffff0000u);
            float f2 = __uint_as_float(h23 << 16);
            float f3 = __uint_as_float(h23 & 0xffff0000u);
            *(uint2*)(AhG + rr * ROWB + lane * 8) = make_uint2(h01, h23);
            *(uint2*)(AlG + rr * ROWB + lane * 8) =
                make_uint2(pack_bf16(v.x - f0, v.y - f1), pack_bf16(v.z - f2, v.w - f3));
        }
        group_bar(g);

        float acc[2][4][4];

        if (MODE == 2) {
            // phase 1: h = relu(A @ W1 + b1) -> back into AhG/AlG
#pragma unroll
            for (int nt = 0; nt < 4; ++nt) {
                int c = N0 + nt * 8 + (lane & 3) * 2;
                float bb0 = b1s[c], bb1 = b1s[c + 1];
#pragma unroll
                for (int mt = 0; mt < 2; ++mt) {
                    acc[mt][nt][0] = bb0; acc[mt][nt][1] = bb1;
                    acc[mt][nt][2] = bb0; acc[mt][nt][3] = bb1;
                }
            }
            gemm_phase(aH, aL, w1H, w1L, acc);
            group_bar(g);
#pragma unroll
            for (int mt = 0; mt < 2; ++mt) {
#pragma unroll
                for (int nt = 0; nt < 4; ++nt) {
                    int r = mt * 16 + (lane >> 2);
                    int c = N0 + nt * 8 + (lane & 3) * 2;
                    float v0 = fmaxf(acc[mt][nt][0], 0.f), v1 = fmaxf(acc[mt][nt][1], 0.f);
                    float v2 = fmaxf(acc[mt][nt][2], 0.f), v3 = fmaxf(acc[mt][nt][3], 0.f);
                    uint32_t h01 = pack_bf16(v0, v1), h23 = pack_bf16(v2, v3);
                    float f0 = __uint_as_float(h01 << 16);
                    float f1 = __uint_as_float(h01 & 0xffff0000u);
                    float f2 = __uint_as_float(h23 << 16);
                    float f3 = __uint_as_float(h23 & 0xffff0000u);
                    *(uint32_t*)(AhG + r * ROWB + c * 2)       = h01;
                    *(uint32_t*)(AhG + (r + 8) * ROWB + c * 2) = h23;
                    *(uint32_t*)(AlG + r * ROWB + c * 2)       = pack_bf16(v0 - f0, v1 - f1);
                    *(uint32_t*)(AlG + (r + 8) * ROWB + c * 2) = pack_bf16(v2 - f2, v3 - f3);
                }
            }
            group_bar(g);
        }

        // phase 2
        if (MODE == 0) {
#pragma unroll
            for (int mt = 0; mt < 2; ++mt)
#pragma unroll
                for (int nt = 0; nt < 4; ++nt)
                    acc[mt][nt][0] = acc[mt][nt][1] = acc[mt][nt][2] = acc[mt][nt][3] = 0.f;
        } else {
#pragma unroll
            for (int nt = 0; nt < 4; ++nt) {
                int c = N0 + nt * 8 + (lane & 3) * 2;
                float bb0 = b2s[c], bb1 = b2s[c + 1];
#pragma unroll
                for (int mt = 0; mt < 2; ++mt) {
                    acc[mt][nt][0] = bb0; acc[mt][nt][1] = bb1;
                    acc[mt][nt][2] = bb0; acc[mt][nt][3] = bb1;
                }
            }
        }
        gemm_phase(aH, aL, w2H, w2L, acc);

        // ---- epilogue ----
#pragma unroll
        for (int mt = 0; mt < 2; ++mt) {
            int r = row0 + mt * 16 + (lane >> 2);
            int bi0 = 0, bi8 = 0;
            if (pbatch) {
                if (r < nRows)     bi0 = pbatch[r];
                if (r + 8 < nRows) bi8 = pbatch[r + 8];
            }
#pragma unroll
            for (int nt = 0; nt < 4; ++nt) {
                int c = N0 + nt * 8 + (lane & 3) * 2;
                float v0 = acc[mt][nt][0], v1 = acc[mt][nt][1];
                float v2 = acc[mt][nt][2], v3 = acc[mt][nt][3];
                if (MODE != 0) {
                    v0 = fmaxf(v0, 0.f); v1 = fmaxf(v1, 0.f);
                    v2 = fmaxf(v2, 0.f); v3 = fmaxf(v3, 0.f);
                }
                if (pbatch) {
                    if (r < nRows) {
                        float* p = g_pool + bi0 * D + c;
                        asm volatile("red.global.add.v2.f32 [%0], {%1, %2};"
                                     :: "l"(p), "f"(v0), "f"(v1) : "memory");
                    }
                    if (r + 8 < nRows) {
                        float* p = g_pool + bi8 * D + c;
                        asm volatile("red.global.add.v2.f32 [%0], {%1, %2};"
                                     :: "l"(p), "f"(v2), "f"(v3) : "memory");
                    }
                } else {
                    if (r < nRows)
                        *(float2*)(out + (size_t)r * D + c) = make_float2(v0, v1);
                    if (r + 8 < nRows)
                        *(float2*)(out + (size_t)(r + 8) * D + c) = make_float2(v2, v3);
                }
            }
        }
    }
}

// ---------------- classifier ------------------------------------------------
__global__ void classifier_kernel(const int* __restrict__ batch, int nNodes,
                                  const float* __restrict__ w1,
                                  const float* __restrict__ b1,
                                  const float* __restrict__ w2,
                                  const float* __restrict__ b2,
                                  float* __restrict__ out) {
    __shared__ float gs[D];
    __shared__ float hs[64];
    __shared__ float cnt_s;
    const int b = blockIdx.x;
    const int t = threadIdx.x;

    if (t == 0) {
        int lo = 0, hi = nNodes;
        while (lo < hi) { int m = (lo + hi) >> 1; if (batch[m] < b) lo = m + 1; else hi = m; }
        int start = lo;
        lo = start; hi = nNodes;
        while (lo < hi) { int m = (lo + hi) >> 1; if (batch[m] <= b) lo = m + 1; else hi = m; }
        cnt_s = fmaxf((float)(lo - start), 1.0f);
    }
    __syncthreads();

    gs[t] = g_pool[b * D + t] / cnt_s;
    __syncthreads();

    if (t < 64) {
        float h = b1[t];
#pragma unroll 8
        for (int k = 0; k < D; ++k) h += gs[k] * w1[k * 64 + t];
        hs[t] = fmaxf(h, 0.f);
    }
    __syncthreads();

    if (t == 0) {
        float o0 = b2[0], o1 = b2[1];
#pragma unroll 8
        for (int j = 0; j < 64; ++j) {
            o0 += hs[j] * w2[2 * j];
            o1 += hs[j] * w2[2 * j + 1];
        }
        float m = fmaxf(o0, o1);
        float e0 = expf(o0 - m), e1 = expf(o1 - m);
        float s = e0 + e1;
        out[2 * b]     = e0 / s;
        out[2 * b + 1] = e1 / s;
    }
}

// ---------------------------------------------------------------------------
extern "C" void kernel_launch(void* const* d_in, const int* in_sizes, int n_in,
                              void* d_out, int out_size) {
    const int*   x_idx   = (const int*)d_in[0];
    const int*   edge    = (const int*)d_in[1];
    const int*   batch   = (const int*)d_in[2];
    const float* emb     = (const float*)d_in[3];
    const float* conv_w1 = (const float*)d_in[4];
    const float* conv_b1 = (const float*)d_in[5];
    const float* conv_w2 = (const float*)d_in[6];
    const float* conv_b2 = (const float*)d_in[7];
    const float* mlp_w1  = (const float*)d_in[8];
    const float* mlp_b1  = (const float*)d_in[9];
    const float* mlp_w2  = (const float*)d_in[10];
    const float* mlp_b2  = (const float*)d_in[11];
    float* out = (float*)d_out;

    const int nNodes = in_sizes[0];
    const int nEdges = in_sizes[1] / 2;
    const int nVocab = in_sizes[3] / D;
    const int* src = edge;
    const int* dst = edge + nEdges;

    float *px, *py, *pembT;
    cudaGetSymbolAddress((void**)&px,    g_x);
    cudaGetSymbolAddress((void**)&py,    g_y);
    cudaGetSymbolAddress((void**)&pembT, g_embT);

    const int smem_small = 4 * TILE_B;   // 139264
    const int smem_big   = 6 * TILE_B;   // 208896
    cudaFuncSetAttribute(mlp_mma<0>, cudaFuncAttributeMaxDynamicSharedMemorySize, smem_small);
    cudaFuncSetAttribute(mlp_mma<1>, cudaFuncAttributeMaxDynamicSharedMemorySize, smem_small);
    cudaFuncSetAttribute(mlp_mma<2>, cudaFuncAttributeMaxDynamicSharedMemorySize, smem_big);

    const int nodeTiles = (nNodes + TMG - 1) / TMG;    // 32-row tiles
    const int embTiles  = (nVocab + TMG - 1) / TMG;
    const int grid1 = (nodeTiles + NGROUP - 1) / NGROUP < 148
                          ? (nodeTiles + NGROUP - 1) / NGROUP : 148;
    const int gridE = (embTiles + NGROUP - 1) / NGROUP < 148
                          ? (embTiles + NGROUP - 1) / NGROUP : 148;
    const int nb = (nNodes + SCAN_BLK - 1) / SCAN_BLK;

    // CSR build + zeros + weight prep
    zero_kernel<<<256, 256>>>();
    prep_weights<<<(6 * D * D + 255) / 256, 256>>>(conv_w1, conv_w2);
    hist_kernel<<<(nEdges + 255) / 256, 256>>>(dst, nEdges);
    scanA_kernel<<<nb, SCAN_BLK>>>(nNodes);
    scanB_kernel<<<1, NB_MAX>>>(nb);
    scanC_kernel<<<nb, SCAN_BLK>>>(nNodes);
    fill_kernel<<<(nEdges + 255) / 256, 256>>>(src, dst, nEdges);

    // embT = emb @ conv_w1[0]
    mlp_mma<0><<<gridE, NT_MLP, smem_small>>>(emb, nullptr, -1, 0, nullptr, nullptr,
                                              pembT, nullptr, nVocab, embTiles);

    // layer 0 (fused gather + aggregate): embT[x_idx] pull -> px
    mlp_mma<1><<<grid1, NT_MLP, smem_small>>>(nullptr, x_idx, -1, 3, conv_b1, conv_b2,
                                              px, nullptr, nNodes, nodeTiles);

    // layer 1: px -> py
    mlp_mma<2><<<grid1, NT_MLP, smem_big>>>(px, nullptr, 1, 4, conv_b1 + D, conv_b2 + D,
                                            py, nullptr, nNodes, nodeTiles);

    // layer 2: py -> pooled sums
    mlp_mma<2><<<grid1, NT_MLP, smem_big>>>(py, nullptr, 2, 5, conv_b1 + 2 * D,
                                            conv_b2 + 2 * D, nullptr, batch,
                                            nNodes, nodeTiles);

    // classifier + softmax
    classifier_kernel<<<N_GRAPHS, D>>>(batch, nNodes, mlp_w1, mlp_b1, mlp_w2,
                                       mlp_b2, out);
}

// round 13
// speedup vs baseline: 2.1376x; 1.1672x over previous
#include <cuda_runtime.h>
#include <cuda_fp16.h>
#include <math.h>
#include <stdint.h>

// Problem constants
#define N_NODES   100000
#define N_EDGES   600000
#define N_GRAPHS  1000
#define VOCAB     10000
#define D         128
#define TMG       32               // rows per GROUP tile
#define NGROUP    4                // groups per CTA
#define GW        4                // warps per group
#define ROWB      272              // padded smem row stride in bytes (136 fp16)
#define TILE_B    (128 * ROWB)
#define QUART_B   (32 * ROWB)
#define NT_MLP    512              // 16 warps: 4 groups x 4 warps
#define SCAN_BLK  1024
#define NB_MAX    128

// ---------------- scratch -------------------------------------------------
__device__ float g_x[N_NODES * D];
__device__ float g_y[N_NODES * D];
__device__ float g_embT[VOCAB * D];
__device__ float g_pool[N_GRAPHS * D];
__device__ int   g_cnt[N_NODES];
__device__ int   g_cur[N_NODES];
__device__ int   g_rowptr[N_NODES + 1];
__device__ int   g_adj[N_EDGES];
__device__ int   g_bsum[NB_MAX];
__device__ int   g_boff[NB_MAX];
// fp16 weights, transposed [n][k]; mats 0..2 = conv_w1[L], 3..5 = conv_w2[L]
__device__ __half g_wf[6][D * D];

// ---------------- helpers -------------------------------------------------
__device__ __forceinline__ uint32_t smem_u32(const void* p) {
    uint32_t a;
    asm("{ .reg .u64 t; cvta.to.shared.u64 t, %1; cvt.u32.u64 %0, t; }"
        : "=r"(a) : "l"(p));
    return a;
}

__device__ __forceinline__ uint32_t pack_f16(float a, float b) {
    __half2 t;
    t.x = __float2half_rn(a);
    t.y = __float2half_rn(b);
    return *(uint32_t*)&t;
}

__device__ __forceinline__ void mma16816(float* d, uint32_t a0, uint32_t a1,
                                         uint32_t a2, uint32_t a3,
                                         uint32_t b0, uint32_t b1) {
    asm volatile(
        "mma.sync.aligned.m16n8k16.row.col.f32.f16.f16.f32 "
        "{%0,%1,%2,%3}, {%4,%5,%6,%7}, {%8,%9}, {%0,%1,%2,%3};\n"
        : "+f"(d[0]), "+f"(d[1]), "+f"(d[2]), "+f"(d[3])
        : "r"(a0), "r"(a1), "r"(a2), "r"(a3), "r"(b0), "r"(b1));
}

__device__ __forceinline__ void ldm_x4(uint32_t& r0, uint32_t& r1, uint32_t& r2,
                                       uint32_t& r3, uint32_t addr) {
    asm volatile("ldmatrix.sync.aligned.m8n8.x4.shared.b16 {%0,%1,%2,%3}, [%4];"
                 : "=r"(r0), "=r"(r1), "=r"(r2), "=r"(r3) : "r"(addr));
}

__device__ __forceinline__ void ldm_x2(uint32_t& r0, uint32_t& r1, uint32_t addr) {
    asm volatile("ldmatrix.sync.aligned.m8n8.x2.shared.b16 {%0,%1}, [%2];"
                 : "=r"(r0), "=r"(r1) : "r"(addr));
}

__device__ __forceinline__ void group_bar(int g) {
    asm volatile("bar.sync %0, %1;" :: "r"(g + 1), "r"(GW * 32) : "memory");
}

// ---------------- CSR build -------------------------------------------------
__global__ void zero_kernel() {
    int i = blockIdx.x * blockDim.x + threadIdx.x;
    int n = gridDim.x * blockDim.x;
    for (int j = i; j < N_NODES; j += n) g_cnt[j] = 0;
    for (int j = i; j < N_GRAPHS * D; j += n) g_pool[j] = 0.0f;
}

__global__ void hist_kernel(const int* __restrict__ dst, int nE) {
    int i = blockIdx.x * blockDim.x + threadIdx.x;
    if (i < nE) atomicAdd(&g_cnt[dst[i]], 1);
}

__global__ void __launch_bounds__(SCAN_BLK, 1) scanA_kernel(int nNodes) {
    __shared__ int red[SCAN_BLK];
    int i = blockIdx.x * SCAN_BLK + threadIdx.x;
    int v = (i < nNodes) ? g_cnt[i] : 0;
    red[threadIdx.x] = v;
    __syncthreads();
    for (int off = SCAN_BLK / 2; off > 0; off >>= 1) {
        if (threadIdx.x < off) red[threadIdx.x] += red[threadIdx.x + off];
        __syncthreads();
    }
    if (threadIdx.x == 0) g_bsum[blockIdx.x] = red[0];
}

__global__ void __launch_bounds__(NB_MAX, 1) scanB_kernel(int nb) {
    __shared__ int s[NB_MAX];
    int t = threadIdx.x;
    int v = (t < nb) ? g_bsum[t] : 0;
    s[t] = v;
    __syncthreads();
    for (int off = 1; off < NB_MAX; off <<= 1) {
        int u = (t >= off) ? s[t - off] : 0;
        __syncthreads();
        s[t] += u;
        __syncthreads();
    }
    if (t < nb) g_boff[t] = s[t] - v;
}

__global__ void __launch_bounds__(SCAN_BLK, 1) scanC_kernel(int nNodes) {
    __shared__ int s[SCAN_BLK];
    int i = blockIdx.x * SCAN_BLK + threadIdx.x;
    int t = threadIdx.x;
    int v = (i < nNodes) ? g_cnt[i] : 0;
    s[t] = v;
    __syncthreads();
    for (int off = 1; off < SCAN_BLK; off <<= 1) {
        int u = (t >= off) ? s[t - off] : 0;
        __syncthreads();
        s[t] += u;
        __syncthreads();
    }
    if (i < nNodes) {
        int excl = s[t] - v + g_boff[blockIdx.x];
        g_rowptr[i] = excl;
        g_cur[i] = excl;
        if (i == nNodes - 1) g_rowptr[nNodes] = excl + v;
    }
}

__global__ void fill_kernel(const int* __restrict__ src,
                            const int* __restrict__ dst, int nE) {
    int i = blockIdx.x * blockDim.x + threadIdx.x;
    if (i >= nE) return;
    int pos = atomicAdd(&g_cur[dst[i]], 1);
    g_adj[pos] = src[i];
}

// ---------------- weight prep -----------------------------------------------
__global__ void prep_weights(const float* __restrict__ w1,
                             const float* __restrict__ w2) {
    int i = blockIdx.x * blockDim.x + threadIdx.x;
    if (i >= 6 * D * D) return;
    int m = i / (D * D), kn = i % (D * D);
    int k = kn / D, n = kn % D;
    float v = (m < 3) ? w1[m * D * D + kn] : w2[(m - 3) * D * D + kn];
    g_wf[m][n * D + k] = __float2half_rn(v);
}

// ---------------- GEMM phase (per warp: 32x32 patch; 2-term fp16) -----------
__device__ __forceinline__ void gemm_phase(uint32_t aH, uint32_t aL, uint32_t bH,
                                           float (&acc)[2][4][4]) {
#pragma unroll
    for (int k0 = 0; k0 < D; k0 += 16) {
        uint32_t ah0[2], ah1[2], ah2[2], ah3[2];
        uint32_t al0[2], al1[2], al2[2], al3[2];
        uint32_t bh0[4], bh1[4];
#pragma unroll
        for (int mt = 0; mt < 2; ++mt) {
            ldm_x4(ah0[mt], ah1[mt], ah2[mt], ah3[mt], aH + mt * (16 * ROWB) + k0 * 2);
            ldm_x4(al0[mt], al1[mt], al2[mt], al3[mt], aL + mt * (16 * ROWB) + k0 * 2);
        }
#pragma unroll
        for (int nt = 0; nt < 4; ++nt)
            ldm_x2(bh0[nt], bh1[nt], bH + nt * (8 * ROWB) + k0 * 2);
#pragma unroll
        for (int mt = 0; mt < 2; ++mt) {
#pragma unroll
            for (int nt = 0; nt < 4; ++nt) {
                mma16816(acc[mt][nt], ah0[mt], ah1[mt], ah2[mt], ah3[mt], bh0[nt], bh1[nt]);
                mma16816(acc[mt][nt], al0[mt], al1[mt], al2[mt], al3[mt], bh0[nt], bh1[nt]);
            }
        }
    }
}

// ---- batched CSR gather: agg = base + sum_{j in [e0,e1)} rows[idx(j)] ------
__device__ __forceinline__ float4 gather_sum(const float* __restrict__ rows,
                                             const int* __restrict__ xidx,
                                             int e0, int e1, int c4, float4 v) {
    int j = e0;
    for (; j + 4 <= e1; j += 4) {
        int n0 = g_adj[j], n1 = g_adj[j + 1], n2 = g_adj[j + 2], n3 = g_adj[j + 3];
        if (xidx) { n0 = xidx[n0]; n1 = xidx[n1]; n2 = xidx[n2]; n3 = xidx[n3]; }
        float4 u0 = *(const float4*)(rows + (size_t)n0 * D + c4);
        float4 u1 = *(const float4*)(rows + (size_t)n1 * D + c4);
        float4 u2 = *(const float4*)(rows + (size_t)n2 * D + c4);
        float4 u3 = *(const float4*)(rows + (size_t)n3 * D + c4);
        v.x += u0.x + u1.x + u2.x + u3.x;
        v.y += u0.y + u1.y + u2.y + u3.y;
        v.z += u0.z + u1.z + u2.z + u3.z;
        v.w += u0.w + u1.w + u2.w + u3.w;
    }
    int rem = e1 - j;
    float4 u0, u1, u2;
    if (rem > 0) {
        int n0 = g_adj[j];
        if (xidx) n0 = xidx[n0];
        u0 = *(const float4*)(rows + (size_t)n0 * D + c4);
    }
    if (rem > 1) {
        int n1 = g_adj[j + 1];
        if (xidx) n1 = xidx[n1];
        u1 = *(const float4*)(rows + (size_t)n1 * D + c4);
    }
    if (rem > 2) {
        int n2 = g_adj[j + 2];
        if (xidx) n2 = xidx[n2];
        u2 = *(const float4*)(rows + (size_t)n2 * D + c4);
    }
    if (rem > 0) { v.x += u0.x; v.y += u0.y; v.z += u0.z; v.w += u0.w; }
    if (rem > 1) { v.x += u1.x; v.y += u1.y; v.z += u1.z; v.w += u1.w; }
    if (rem > 2) { v.x += u2.x; v.y += u2.y; v.z += u2.z; v.w += u2.w; }
    return v;
}

// ---------------- persistent fused aggregate+MLP, 4 groups per CTA ----------
// MODE 0: out = x @ W[w2_id]
// MODE 1: A = sum embT[x_idx[self+nbrs]]; h = relu(A + b1); out = relu(h@W2 + b2)
// MODE 2: A = x[self] + sum x[nbrs]; h = relu(A@W1 + b1); out = relu(h@W2 + b2)
// pbatch != nullptr: red.add result into g_pool[batch[row]] instead of out.
template <int MODE>
__global__ void __launch_bounds__(NT_MLP, 1)
mlp_mma(const float* __restrict__ x, const int* __restrict__ xidx,
        int w1_id, int w2_id,
        const float* __restrict__ b1, const float* __restrict__ b2,
        float* __restrict__ out, const int* __restrict__ pbatch,
        int nRows, int nTiles) {
    extern __shared__ __align__(16) unsigned char sm[];
    unsigned char* Ah = sm;                  // 128 rows: group g owns rows [32g, 32g+32)
    unsigned char* Al = sm + TILE_B;
    unsigned char* W2 = sm + 2 * TILE_B;
    unsigned char* W1 = sm + 3 * TILE_B;     // MODE 2 only
    __shared__ float b1s[D], b2s[D];

    const int tid  = threadIdx.x;
    const int lane = tid & 31, wid = tid >> 5;
    const int g    = wid >> 2;               // group 0..3
    const int wg   = wid & 3;                // warp within group
    const int N0 = wg * 32;                  // each warp: rows 0..31 x cols N0..N0+31

    if (MODE != 0 && tid < D) {
        b2s[tid] = b2[tid];
        if (MODE == 2) b1s[tid] = b1[tid];
    }

    // stage weights once (all 16 warps); fp16 tables
    {
        const uint4* s2 = (const uint4*)g_wf[w2_id];
        for (int i = tid; i < 128 * 16; i += NT_MLP) {
            int n = i >> 4, c = i & 15;
            *(uint4*)(W2 + n * ROWB + c * 16) = s2[n * 16 + c];
        }
        if (MODE == 2) {
            const uint4* s1 = (const uint4*)g_wf[w1_id];
            for (int i = tid; i < 128 * 16; i += NT_MLP) {
                int n = i >> 4, c = i & 15;
                *(uint4*)(W1 + n * ROWB + c * 16) = s1[n * 16 + c];
            }
        }
    }
    __syncthreads();     // weights visible to all groups; last full-CTA barrier

    // group-local A-quarter base and per-lane addresses
    unsigned char* AhG = Ah + g * QUART_B;
    unsigned char* AlG = Al + g * QUART_B;
    const uint32_t aOff = (uint32_t)(lane & 15) * ROWB + ((lane >> 4) * 16);
    const uint32_t bOff = (uint32_t)(N0 + (lane & 7)) * ROWB + (((lane >> 3) & 1) * 16);
    const uint32_t aH = smem_u32(AhG) + aOff, aL = smem_u32(AlG) + aOff;
    const uint32_t w2H = smem_u32(W2) + bOff;
    const uint32_t w1H = (MODE == 2) ? smem_u32(W1) + bOff : 0;

    for (int t = blockIdx.x * NGROUP + g; t < nTiles; t += gridDim.x * NGROUP) {
        const int row0 = t * TMG;
        group_bar(g);   // protect this group's A quarter from previous iteration

        // ---- fused aggregate + fp16-split-convert A quarter (warp per row) ----
        for (int rr = wg; rr < TMG; rr += GW) {
            const int gr = row0 + rr;
            float4 v = make_float4(0.f, 0.f, 0.f, 0.f);
            if (gr < nRows) {
                const int c4 = lane * 4;
                if (MODE == 0) {
                    v = *(const float4*)(x + (size_t)gr * D + c4);
                } else if (MODE == 1) {
                    int self = xidx[gr];
                    int e0 = g_rowptr[gr], e1 = g_rowptr[gr + 1];
                    v = *(const float4*)(g_embT + (size_t)self * D + c4);
                    v = gather_sum(g_embT, xidx, e0, e1, c4, v);
                    float4 bv = *(const float4*)(b1 + c4);
                    v.x = fmaxf(v.x + bv.x, 0.f); v.y = fmaxf(v.y + bv.y, 0.f);
                    v.z = fmaxf(v.z + bv.z, 0.f); v.w = fmaxf(v.w + bv.w, 0.f);
                } else {
                    int e0 = g_rowptr[gr], e1 = g_rowptr[gr + 1];
                    v = *(const float4*)(x + (size_t)gr * D + c4);
                    v = gather_sum(x, nullptr, e0, e1, c4, v);
                }
            }
            __half h0 = __float2half_rn(v.x), h1 = __float2half_rn(v.y);
            __half h2 = __float2half_rn(v.z), h3 = __float2half_rn(v.w);
            __half2 p01; p01.x = h0; p01.y = h1;
            __half2 p23; p23.x = h2; p23.y = h3;
            *(uint2*)(AhG + rr * ROWB + lane * 8) =
                make_uint2(*(uint32_t*)&p01, *(uint32_t*)&p23);
            *(uint2*)(AlG + rr * ROWB + lane * 8) =
                make_uint2(pack_f16(v.x - __half2float(h0), v.y - __half2float(h1)),
                           pack_f16(v.z - __half2float(h2), v.w - __half2float(h3)));
        }
        group_bar(g);

        float acc[2][4][4];

        if (MODE == 2) {
            // phase 1: h = relu(A @ W1 + b1) -> back into AhG/AlG
#pragma unroll
            for (int nt = 0; nt < 4; ++nt) {
                int c = N0 + nt * 8 + (lane & 3) * 2;
                float bb0 = b1s[c], bb1 = b1s[c + 1];
#pragma unroll
                for (int mt = 0; mt < 2; ++mt) {
                    acc[mt][nt][0] = bb0; acc[mt][nt][1] = bb1;
                    acc[mt][nt][2] = bb0; acc[mt][nt][3] = bb1;
                }
            }
            gemm_phase(aH, aL, w1H, acc);
            group_bar(g);
#pragma unroll
            for (int mt = 0; mt < 2; ++mt) {
#pragma unroll
                for (int nt = 0; nt < 4; ++nt) {
                    int r = mt * 16 + (lane >> 2);
                    int c = N0 + nt * 8 + (lane & 3) * 2;
                    float v0 = fmaxf(acc[mt][nt][0], 0.f), v1 = fmaxf(acc[mt][nt][1], 0.f);
                    float v2 = fmaxf(acc[mt][nt][2], 0.f), v3 = fmaxf(acc[mt][nt][3], 0.f);
                    __half h0 = __float2half_rn(v0), h1 = __float2half_rn(v1);
                    __half h2 = __float2half_rn(v2), h3 = __float2half_rn(v3);
                    __half2 p01; p01.x = h0; p01.y = h1;
                    __half2 p23; p23.x = h2; p23.y = h3;
                    *(uint32_t*)(AhG + r * ROWB + c * 2)       = *(uint32_t*)&p01;
                    *(uint32_t*)(AhG + (r + 8) * ROWB + c * 2) = *(uint32_t*)&p23;
                    *(uint32_t*)(AlG + r * ROWB + c * 2) =
                        pack_f16(v0 - __half2float(h0), v1 - __half2float(h1));
                    *(uint32_t*)(AlG + (r + 8) * ROWB + c * 2) =
                        pack_f16(v2 - __half2float(h2), v3 - __half2float(h3));
                }
            }
            group_bar(g);
        }

        // phase 2
        if (MODE == 0) {
#pragma unroll
            for (int mt = 0; mt < 2; ++mt)
#pragma unroll
                for (int nt = 0; nt < 4; ++nt)
                    acc[mt][nt][0] = acc[mt][nt][1] = acc[mt][nt][2] = acc[mt][nt][3] = 0.f;
        } else {
#pragma unroll
            for (int nt = 0; nt < 4; ++nt) {
                int c = N0 + nt * 8 + (lane & 3) * 2;
                float bb0 = b2s[c], bb1 = b2s[c + 1];
#pragma unroll
                for (int mt = 0; mt < 2; ++mt) {
                    acc[mt][nt][0] = bb0; acc[mt][nt][1] = bb1;
                    acc[mt][nt][2] = bb0; acc[mt][nt][3] = bb1;
                }
            }
        }
        gemm_phase(aH, aL, w2H, acc);

        // ---- epilogue ----
#pragma unroll
        for (int mt = 0; mt < 2; ++mt) {
            int r = row0 + mt * 16 + (lane >> 2);
            int bi0 = 0, bi8 = 0;
            if (pbatch) {
                if (r < nRows)     bi0 = pbatch[r];
                if (r + 8 < nRows) bi8 = pbatch[r + 8];
            }
#pragma unroll
            for (int nt = 0; nt < 4; ++nt) {
                int c = N0 + nt * 8 + (lane & 3) * 2;
                float v0 = acc[mt][nt][0], v1 = acc[mt][nt][1];
                float v2 = acc[mt][nt][2], v3 = acc[mt][nt][3];
                if (MODE != 0) {
                    v0 = fmaxf(v0, 0.f); v1 = fmaxf(v1, 0.f);
                    v2 = fmaxf(v2, 0.f); v3 = fmaxf(v3, 0.f);
                }
                if (pbatch) {
                    if (r < nRows) {
                        float* p = g_pool + bi0 * D + c;
                        asm volatile("red.global.add.v2.f32 [%0], {%1, %2};"
                                     :: "l"(p), "f"(v0), "f"(v1) : "memory");
                    }
                    if (r + 8 < nRows) {
                        float* p = g_pool + bi8 * D + c;
                        asm volatile("red.global.add.v2.f32 [%0], {%1, %2};"
                                     :: "l"(p), "f"(v2), "f"(v3) : "memory");
                    }
                } else {
                    if (r < nRows)
                        *(float2*)(out + (size_t)r * D + c) = make_float2(v0, v1);
                    if (r + 8 < nRows)
                        *(float2*)(out + (size_t)(r + 8) * D + c) = make_float2(v2, v3);
                }
            }
        }
    }
}

// ---------------- classifier ------------------------------------------------
__global__ void classifier_kernel(const int* __restrict__ batch, int nNodes,
                                  const float* __restrict__ w1,
                                  const float* __restrict__ b1,
                                  const float* __restrict__ w2,
                                  const float* __restrict__ b2,
                                  float* __restrict__ out) {
    __shared__ float gs[D];
    __shared__ float hs[64];
    __shared__ float cnt_s;
    const int b = blockIdx.x;
    const int t = threadIdx.x;

    if (t == 0) {
        int lo = 0, hi = nNodes;
        while (lo < hi) { int m = (lo + hi) >> 1; if (batch[m] < b) lo = m + 1; else hi = m; }
        int start = lo;
        lo = start; hi = nNodes;
        while (lo < hi) { int m = (lo + hi) >> 1; if (batch[m] <= b) lo = m + 1; else hi = m; }
        cnt_s = fmaxf((float)(lo - start), 1.0f);
    }
    __syncthreads();

    gs[t] = g_pool[b * D + t] / cnt_s;
    __syncthreads();

    if (t < 64) {
        float h = b1[t];
#pragma unroll 8
        for (int k = 0; k < D; ++k) h += gs[k] * w1[k * 64 + t];
        hs[t] = fmaxf(h, 0.f);
    }
    __syncthreads();

    if (t == 0) {
        float o0 = b2[0], o1 = b2[1];
#pragma unroll 8
        for (int j = 0; j < 64; ++j) {
            o0 += hs[j] * w2[2 * j];
            o1 += hs[j] * w2[2 * j + 1];
        }
        float m = fmaxf(o0, o1);
        float e0 = expf(o0 - m), e1 = expf(o1 - m);
        float s = e0 + e1;
        out[2 * b]     = e0 / s;
        out[2 * b + 1] = e1 / s;
    }
}

// ---------------------------------------------------------------------------
extern "C" void kernel_launch(void* const* d_in, const int* in_sizes, int n_in,
                              void* d_out, int out_size) {
    const int*   x_idx   = (const int*)d_in[0];
    const int*   edge    = (const int*)d_in[1];
    const int*   batch   = (const int*)d_in[2];
    const float* emb     = (const float*)d_in[3];
    const float* conv_w1 = (const float*)d_in[4];
    const float* conv_b1 = (const float*)d_in[5];
    const float* conv_w2 = (const float*)d_in[6];
    const float* conv_b2 = (const float*)d_in[7];
    const float* mlp_w1  = (const float*)d_in[8];
    const float* mlp_b1  = (const float*)d_in[9];
    const float* mlp_w2  = (const float*)d_in[10];
    const float* mlp_b2  = (const float*)d_in[11];
    float* out = (float*)d_out;

    const int nNodes = in_sizes[0];
    const int nEdges = in_sizes[1] / 2;
    const int nVocab = in_sizes[3] / D;
    const int* src = edge;
    const int* dst = edge + nEdges;

    float *px, *py, *pembT;
    cudaGetSymbolAddress((void**)&px,    g_x);
    cudaGetSymbolAddress((void**)&py,    g_y);
    cudaGetSymbolAddress((void**)&pembT, g_embT);

    const int smem_small = 3 * TILE_B;   // 104448
    const int smem_big   = 4 * TILE_B;   // 139264
    cudaFuncSetAttribute(mlp_mma<0>, cudaFuncAttributeMaxDynamicSharedMemorySize, smem_small);
    cudaFuncSetAttribute(mlp_mma<1>, cudaFuncAttributeMaxDynamicSharedMemorySize, smem_small);
    cudaFuncSetAttribute(mlp_mma<2>, cudaFuncAttributeMaxDynamicSharedMemorySize, smem_big);

    const int nodeTiles = (nNodes + TMG - 1) / TMG;    // 32-row tiles
    const int embTiles  = (nVocab + TMG - 1) / TMG;
    const int grid1 = (nodeTiles + NGROUP - 1) / NGROUP < 148
                          ? (nodeTiles + NGROUP - 1) / NGROUP : 148;
    const int gridE = (embTiles + NGROUP - 1) / NGROUP < 148
                          ? (embTiles + NGROUP - 1) / NGROUP : 148;
    const int nb = (nNodes + SCAN_BLK - 1) / SCAN_BLK;

    // CSR build + zeros + weight prep
    zero_kernel<<<256, 256>>>();
    prep_weights<<<(6 * D * D + 255) / 256, 256>>>(conv_w1, conv_w2);
    hist_kernel<<<(nEdges + 255) / 256, 256>>>(dst, nEdges);
    scanA_kernel<<<nb, SCAN_BLK>>>(nNodes);
    scanB_kernel<<<1, NB_MAX>>>(nb);
    scanC_kernel<<<nb, SCAN_BLK>>>(nNodes);
    fill_kernel<<<(nEdges + 255) / 256, 256>>>(src, dst, nEdges);

    // embT = emb @ conv_w1[0]
    mlp_mma<0><<<gridE, NT_MLP, smem_small>>>(emb, nullptr, -1, 0, nullptr, nullptr,
                                              pembT, nullptr, nVocab, embTiles);

    // layer 0 (fused gather + aggregate): embT[x_idx] pull -> px
    mlp_mma<1><<<grid1, NT_MLP, smem_small>>>(nullptr, x_idx, -1, 3, conv_b1, conv_b2,
                                              px, nullptr, nNodes, nodeTiles);

    // layer 1: px -> py
    mlp_mma<2><<<grid1, NT_MLP, smem_big>>>(px, nullptr, 1, 4, conv_b1 + D, conv_b2 + D,
                                            py, nullptr, nNodes, nodeTiles);

    // layer 2: py -> pooled sums
    mlp_mma<2><<<grid1, NT_MLP, smem_big>>>(py, nullptr, 2, 5, conv_b1 + 2 * D,
                                            conv_b2 + 2 * D, nullptr, batch,
                                            nNodes, nodeTiles);

    // classifier + softmax
    classifier_kernel<<<N_GRAPHS, D>>>(batch, nNodes, mlp_w1, mlp_b1, mlp_w2,
                                       mlp_b2, out);
}

// round 14
// speedup vs baseline: 2.3930x; 1.1195x over previous
#include <cuda_runtime.h>
#include <cuda_fp16.h>
#include <math.h>
#include <stdint.h>

// Problem constants
#define N_NODES   100000
#define N_EDGES   600000
#define N_GRAPHS  1000
#define VOCAB     10000
#define D         128
#define TMG       32               // rows per GROUP tile
#define NGROUP    4                // groups per CTA
#define GW        4                // warps per group
#define ROWB      272              // padded smem row stride in bytes (136 fp16)
#define TILE_B    (128 * ROWB)
#define QUART_B   (32 * ROWB)
#define NT_MLP    512              // 16 warps: 4 groups x 4 warps
#define SCAN_BLK  1024
#define NB_MAX    128

// ---------------- scratch -------------------------------------------------
__device__ float g_x[N_NODES * D];
__device__ float g_y[N_NODES * D];
__device__ float g_embT[VOCAB * D];
__device__ float g_pool[N_GRAPHS * D];
__device__ int   g_cnt[N_NODES];
__device__ int   g_cur[N_NODES];
__device__ int   g_rowptr[N_NODES + 1];
__device__ int   g_adj[N_EDGES];
__device__ int   g_bsum[NB_MAX];
__device__ int   g_boff[NB_MAX];
// fp16 weights, transposed [n][k]; mats 0..2 = conv_w1[L], 3..5 = conv_w2[L]
__device__ __half g_wf[6][D * D];

// ---------------- helpers -------------------------------------------------
__device__ __forceinline__ uint32_t smem_u32(const void* p) {
    uint32_t a;
    asm("{ .reg .u64 t; cvta.to.shared.u64 t, %1; cvt.u32.u64 %0, t; }"
        : "=r"(a) : "l"(p));
    return a;
}

__device__ __forceinline__ void mma16816(float* d, uint32_t a0, uint32_t a1,
                                         uint32_t a2, uint32_t a3,
                                         uint32_t b0, uint32_t b1) {
    asm volatile(
        "mma.sync.aligned.m16n8k16.row.col.f32.f16.f16.f32 "
        "{%0,%1,%2,%3}, {%4,%5,%6,%7}, {%8,%9}, {%0,%1,%2,%3};\n"
        : "+f"(d[0]), "+f"(d[1]), "+f"(d[2]), "+f"(d[3])
        : "r"(a0), "r"(a1), "r"(a2), "r"(a3), "r"(b0), "r"(b1));
}

__device__ __forceinline__ void ldm_x4(uint32_t& r0, uint32_t& r1, uint32_t& r2,
                                       uint32_t& r3, uint32_t addr) {
    asm volatile("ldmatrix.sync.aligned.m8n8.x4.shared.b16 {%0,%1,%2,%3}, [%4];"
                 : "=r"(r0), "=r"(r1), "=r"(r2), "=r"(r3) : "r"(addr));
}

__device__ __forceinline__ void ldm_x2(uint32_t& r0, uint32_t& r1, uint32_t addr) {
    asm volatile("ldmatrix.sync.aligned.m8n8.x2.shared.b16 {%0,%1}, [%2];"
                 : "=r"(r0), "=r"(r1) : "r"(addr));
}

__device__ __forceinline__ void group_bar(int g) {
    asm volatile("bar.sync %0, %1;" :: "r"(g + 1), "r"(GW * 32) : "memory");
}

// ---------------- CSR build -------------------------------------------------
__global__ void zero_kernel() {
    int i = blockIdx.x * blockDim.x + threadIdx.x;
    int n = gridDim.x * blockDim.x;
    for (int j = i; j < N_NODES; j += n) g_cnt[j] = 0;
    for (int j = i; j < N_GRAPHS * D; j += n) g_pool[j] = 0.0f;
}

__global__ void hist_kernel(const int* __restrict__ dst, int nE) {
    int i = blockIdx.x * blockDim.x + threadIdx.x;
    if (i < nE) atomicAdd(&g_cnt[dst[i]], 1);
}

__global__ void __launch_bounds__(SCAN_BLK, 1) scanA_kernel(int nNodes) {
    __shared__ int red[SCAN_BLK];
    int i = blockIdx.x * SCAN_BLK + threadIdx.x;
    int v = (i < nNodes) ? g_cnt[i] : 0;
    red[threadIdx.x] = v;
    __syncthreads();
    for (int off = SCAN_BLK / 2; off > 0; off >>= 1) {
        if (threadIdx.x < off) red[threadIdx.x] += red[threadIdx.x + off];
        __syncthreads();
    }
    if (threadIdx.x == 0) g_bsum[blockIdx.x] = red[0];
}

__global__ void __launch_bounds__(NB_MAX, 1) scanB_kernel(int nb) {
    __shared__ int s[NB_MAX];
    int t = threadIdx.x;
    int v = (t < nb) ? g_bsum[t] : 0;
    s[t] = v;
    __syncthreads();
    for (int off = 1; off < NB_MAX; off <<= 1) {
        int u = (t >= off) ? s[t - off] : 0;
        __syncthreads();
        s[t] += u;
        __syncthreads();
    }
    if (t < nb) g_boff[t] = s[t] - v;
}

__global__ void __launch_bounds__(SCAN_BLK, 1) scanC_kernel(int nNodes) {
    __shared__ int s[SCAN_BLK];
    int i = blockIdx.x * SCAN_BLK + threadIdx.x;
    int t = threadIdx.x;
    int v = (i < nNodes) ? g_cnt[i] : 0;
    s[t] = v;
    __syncthreads();
    for (int off = 1; off < SCAN_BLK; off <<= 1) {
        int u = (t >= off) ? s[t - off] : 0;
        __syncthreads();
        s[t] += u;
        __syncthreads();
    }
    if (i < nNodes) {
        int excl = s[t] - v + g_boff[blockIdx.x];
        g_rowptr[i] = excl;
        g_cur[i] = excl;
        if (i == nNodes - 1) g_rowptr[nNodes] = excl + v;
    }
}

__global__ void fill_kernel(const int* __restrict__ src,
                            const int* __restrict__ dst, int nE) {
    int i = blockIdx.x * blockDim.x + threadIdx.x;
    if (i >= nE) return;
    int pos = atomicAdd(&g_cur[dst[i]], 1);
    g_adj[pos] = src[i];
}

// ---------------- weight prep -----------------------------------------------
__global__ void prep_weights(const float* __restrict__ w1,
                             const float* __restrict__ w2) {
    int i = blockIdx.x * blockDim.x + threadIdx.x;
    if (i >= 6 * D * D) return;
    int m = i / (D * D), kn = i % (D * D);
    int k = kn / D, n = kn % D;
    float v = (m < 3) ? w1[m * D * D + kn] : w2[(m - 3) * D * D + kn];
    g_wf[m][n * D + k] = __float2half_rn(v);
}

// ---------------- GEMM phase (per warp: 32x32 patch; single fp16) -----------
__device__ __forceinline__ void gemm_phase(uint32_t aH, uint32_t bH,
                                           float (&acc)[2][4][4]) {
#pragma unroll
    for (int k0 = 0; k0 < D; k0 += 16) {
        uint32_t ah0[2], ah1[2], ah2[2], ah3[2];
        uint32_t bh0[4], bh1[4];
#pragma unroll
        for (int mt = 0; mt < 2; ++mt)
            ldm_x4(ah0[mt], ah1[mt], ah2[mt], ah3[mt], aH + mt * (16 * ROWB) + k0 * 2);
#pragma unroll
        for (int nt = 0; nt < 4; ++nt)
            ldm_x2(bh0[nt], bh1[nt], bH + nt * (8 * ROWB) + k0 * 2);
#pragma unroll
        for (int mt = 0; mt < 2; ++mt)
#pragma unroll
            for (int nt = 0; nt < 4; ++nt)
                mma16816(acc[mt][nt], ah0[mt], ah1[mt], ah2[mt], ah3[mt], bh0[nt], bh1[nt]);
    }
}

// ---- batched CSR gather: agg = base + sum_{j in [e0,e1)} rows[idx(j)] ------
__device__ __forceinline__ float4 gather_sum(const float* __restrict__ rows,
                                             const int* __restrict__ xidx,
                                             int e0, int e1, int c4, float4 v) {
    int j = e0;
    for (; j + 4 <= e1; j += 4) {
        int n0 = g_adj[j], n1 = g_adj[j + 1], n2 = g_adj[j + 2], n3 = g_adj[j + 3];
        if (xidx) { n0 = xidx[n0]; n1 = xidx[n1]; n2 = xidx[n2]; n3 = xidx[n3]; }
        float4 u0 = *(const float4*)(rows + (size_t)n0 * D + c4);
        float4 u1 = *(const float4*)(rows + (size_t)n1 * D + c4);
        float4 u2 = *(const float4*)(rows + (size_t)n2 * D + c4);
        float4 u3 = *(const float4*)(rows + (size_t)n3 * D + c4);
        v.x += u0.x + u1.x + u2.x + u3.x;
        v.y += u0.y + u1.y + u2.y + u3.y;
        v.z += u0.z + u1.z + u2.z + u3.z;
        v.w += u0.w + u1.w + u2.w + u3.w;
    }
    int rem = e1 - j;
    float4 u0, u1, u2;
    if (rem > 0) {
        int n0 = g_adj[j];
        if (xidx) n0 = xidx[n0];
        u0 = *(const float4*)(rows + (size_t)n0 * D + c4);
    }
    if (rem > 1) {
        int n1 = g_adj[j + 1];
        if (xidx) n1 = xidx[n1];
        u1 = *(const float4*)(rows + (size_t)n1 * D + c4);
    }
    if (rem > 2) {
        int n2 = g_adj[j + 2];
        if (xidx) n2 = xidx[n2];
        u2 = *(const float4*)(rows + (size_t)n2 * D + c4);
    }
    if (rem > 0) { v.x += u0.x; v.y += u0.y; v.z += u0.z; v.w += u0.w; }
    if (rem > 1) { v.x += u1.x; v.y += u1.y; v.z += u1.z; v.w += u1.w; }
    if (rem > 2) { v.x += u2.x; v.y += u2.y; v.z += u2.z; v.w += u2.w; }
    return v;
}

// ---------------- persistent fused aggregate+MLP, 4 groups per CTA ----------
// MODE 0: out = x @ W[w2_id]
// MODE 1: A = sum embT[x_idx[self+nbrs]]; h = relu(A + b1); out = relu(h@W2 + b2)
// MODE 2: A = x[self] + sum x[nbrs]; h = relu(A@W1 + b1); out = relu(h@W2 + b2)
// pbatch != nullptr: red.add result into g_pool[batch[row]] instead of out.
template <int MODE>
__global__ void __launch_bounds__(NT_MLP, 1)
mlp_mma(const float* __restrict__ x, const int* __restrict__ xidx,
        int w1_id, int w2_id,
        const float* __restrict__ b1, const float* __restrict__ b2,
        float* __restrict__ out, const int* __restrict__ pbatch,
        int nRows, int nTiles) {
    extern __shared__ __align__(16) unsigned char sm[];
    unsigned char* Ah = sm;                  // 128 rows: group g owns rows [32g, 32g+32)
    unsigned char* W2 = sm + TILE_B;
    unsigned char* W1 = sm + 2 * TILE_B;     // MODE 2 only
    __shared__ float b1s[D], b2s[D];

    const int tid  = threadIdx.x;
    const int lane = tid & 31, wid = tid >> 5;
    const int g    = wid >> 2;               // group 0..3
    const int wg   = wid & 3;                // warp within group
    const int N0 = wg * 32;                  // each warp: rows 0..31 x cols N0..N0+31

    if (MODE != 0 && tid < D) {
        b2s[tid] = b2[tid];
        if (MODE == 2) b1s[tid] = b1[tid];
    }

    // stage weights once (all 16 warps); fp16 tables
    {
        const uint4* s2 = (const uint4*)g_wf[w2_id];
        for (int i = tid; i < 128 * 16; i += NT_MLP) {
            int n = i >> 4, c = i & 15;
            *(uint4*)(W2 + n * ROWB + c * 16) = s2[n * 16 + c];
        }
        if (MODE == 2) {
            const uint4* s1 = (const uint4*)g_wf[w1_id];
            for (int i = tid; i < 128 * 16; i += NT_MLP) {
                int n = i >> 4, c = i & 15;
                *(uint4*)(W1 + n * ROWB + c * 16) = s1[n * 16 + c];
            }
        }
    }
    __syncthreads();     // weights visible to all groups; last full-CTA barrier

    // group-local A-quarter base and per-lane addresses
    unsigned char* AhG = Ah + g * QUART_B;
    const uint32_t aOff = (uint32_t)(lane & 15) * ROWB + ((lane >> 4) * 16);
    const uint32_t bOff = (uint32_t)(N0 + (lane & 7)) * ROWB + (((lane >> 3) & 1) * 16);
    const uint32_t aH = smem_u32(AhG) + aOff;
    const uint32_t w2H = smem_u32(W2) + bOff;
    const uint32_t w1H = (MODE == 2) ? smem_u32(W1) + bOff : 0;

    for (int t = blockIdx.x * NGROUP + g; t < nTiles; t += gridDim.x * NGROUP) {
        const int row0 = t * TMG;
        group_bar(g);   // protect this group's A quarter from previous iteration

        // ---- fused aggregate + fp16 convert of A quarter (warp per row) ----
        for (int rr = wg; rr < TMG; rr += GW) {
            const int gr = row0 + rr;
            float4 v = make_float4(0.f, 0.f, 0.f, 0.f);
            if (gr < nRows) {
                const int c4 = lane * 4;
                if (MODE == 0) {
                    v = *(const float4*)(x + (size_t)gr * D + c4);
                } else if (MODE == 1) {
                    int self = xidx[gr];
                    int e0 = g_rowptr[gr], e1 = g_rowptr[gr + 1];
                    v = *(const float4*)(g_embT + (size_t)self * D + c4);
                    v = gather_sum(g_embT, xidx, e0, e1, c4, v);
                    float4 bv = *(const float4*)(b1 + c4);
                    v.x = fmaxf(v.x + bv.x, 0.f); v.y = fmaxf(v.y + bv.y, 0.f);
                    v.z = fmaxf(v.z + bv.z, 0.f); v.w = fmaxf(v.w + bv.w, 0.f);
                } else {
                    int e0 = g_rowptr[gr], e1 = g_rowptr[gr + 1];
                    v = *(const float4*)(x + (size_t)gr * D + c4);
                    v = gather_sum(x, nullptr, e0, e1, c4, v);
                }
            }
            __half2 p01; p01.x = __float2half_rn(v.x); p01.y = __float2half_rn(v.y);
            __half2 p23; p23.x = __float2half_rn(v.z); p23.y = __float2half_rn(v.w);
            *(uint2*)(AhG + rr * ROWB + lane * 8) =
                make_uint2(*(uint32_t*)&p01, *(uint32_t*)&p23);
        }
        group_bar(g);

        float acc[2][4][4];

        if (MODE == 2) {
            // phase 1: h = relu(A @ W1 + b1) -> back into AhG
#pragma unroll
            for (int nt = 0; nt < 4; ++nt) {
                int c = N0 + nt * 8 + (lane & 3) * 2;
                float bb0 = b1s[c], bb1 = b1s[c + 1];
#pragma unroll
                for (int mt = 0; mt < 2; ++mt) {
                    acc[mt][nt][0] = bb0; acc[mt][nt][1] = bb1;
                    acc[mt][nt][2] = bb0; acc[mt][nt][3] = bb1;
                }
            }
            gemm_phase(aH, w1H, acc);
            group_bar(g);
#pragma unroll
            for (int mt = 0; mt < 2; ++mt) {
#pragma unroll
                for (int nt = 0; nt < 4; ++nt) {
                    int r = mt * 16 + (lane >> 2);
                    int c = N0 + nt * 8 + (lane & 3) * 2;
                    float v0 = fmaxf(acc[mt][nt][0], 0.f), v1 = fmaxf(acc[mt][nt][1], 0.f);
                    float v2 = fmaxf(acc[mt][nt][2], 0.f), v3 = fmaxf(acc[mt][nt][3], 0.f);
                    __half2 p01; p01.x = __float2half_rn(v0); p01.y = __float2half_rn(v1);
                    __half2 p23; p23.x = __float2half_rn(v2); p23.y = __float2half_rn(v3);
                    *(uint32_t*)(AhG + r * ROWB + c * 2)       = *(uint32_t*)&p01;
                    *(uint32_t*)(AhG + (r + 8) * ROWB + c * 2) = *(uint32_t*)&p23;
                }
            }
            group_bar(g);
        }

        // phase 2
        if (MODE == 0) {
#pragma unroll
            for (int mt = 0; mt < 2; ++mt)
#pragma unroll
                for (int nt = 0; nt < 4; ++nt)
                    acc[mt][nt][0] = acc[mt][nt][1] = acc[mt][nt][2] = acc[mt][nt][3] = 0.f;
        } else {
#pragma unroll
            for (int nt = 0; nt < 4; ++nt) {
                int c = N0 + nt * 8 + (lane & 3) * 2;
                float bb0 = b2s[c], bb1 = b2s[c + 1];
#pragma unroll
                for (int mt = 0; mt < 2; ++mt) {
                    acc[mt][nt][0] = bb0; acc[mt][nt][1] = bb1;
                    acc[mt][nt][2] = bb0; acc[mt][nt][3] = bb1;
                }
            }
        }
        gemm_phase(aH, w2H, acc);

        // ---- epilogue ----
#pragma unroll
        for (int mt = 0; mt < 2; ++mt) {
            int r = row0 + mt * 16 + (lane >> 2);
            int bi0 = 0, bi8 = 0;
            if (pbatch) {
                if (r < nRows)     bi0 = pbatch[r];
                if (r + 8 < nRows) bi8 = pbatch[r + 8];
            }
#pragma unroll
            for (int nt = 0; nt < 4; ++nt) {
                int c = N0 + nt * 8 + (lane & 3) * 2;
                float v0 = acc[mt][nt][0], v1 = acc[mt][nt][1];
                float v2 = acc[mt][nt][2], v3 = acc[mt][nt][3];
                if (MODE != 0) {
                    v0 = fmaxf(v0, 0.f); v1 = fmaxf(v1, 0.f);
                    v2 = fmaxf(v2, 0.f); v3 = fmaxf(v3, 0.f);
                }
                if (pbatch) {
                    if (r < nRows) {
                        float* p = g_pool + bi0 * D + c;
                        asm volatile("red.global.add.v2.f32 [%0], {%1, %2};"
                                     :: "l"(p), "f"(v0), "f"(v1) : "memory");
                    }
                    if (r + 8 < nRows) {
                        float* p = g_pool + bi8 * D + c;
                        asm volatile("red.global.add.v2.f32 [%0], {%1, %2};"
                                     :: "l"(p), "f"(v2), "f"(v3) : "memory");
                    }
                } else {
                    if (r < nRows)
                        *(float2*)(out + (size_t)r * D + c) = make_float2(v0, v1);
                    if (r + 8 < nRows)
                        *(float2*)(out + (size_t)(r + 8) * D + c) = make_float2(v2, v3);
                }
            }
        }
    }
}

// ---------------- classifier ------------------------------------------------
__global__ void classifier_kernel(const int* __restrict__ batch, int nNodes,
                                  const float* __restrict__ w1,
                                  const float* __restrict__ b1,
                                  const float* __restrict__ w2,
                                  const float* __restrict__ b2,
                                  float* __restrict__ out) {
    __shared__ float gs[D];
    __shared__ float hs[64];
    __shared__ float cnt_s;
    const int b = blockIdx.x;
    const int t = threadIdx.x;

    if (t == 0) {
        int lo = 0, hi = nNodes;
        while (lo < hi) { int m = (lo + hi) >> 1; if (batch[m] < b) lo = m + 1; else hi = m; }
        int start = lo;
        lo = start; hi = nNodes;
        while (lo < hi) { int m = (lo + hi) >> 1; if (batch[m] <= b) lo = m + 1; else hi = m; }
        cnt_s = fmaxf((float)(lo - start), 1.0f);
    }
    __syncthreads();

    gs[t] = g_pool[b * D + t] / cnt_s;
    __syncthreads();

    if (t < 64) {
        float h = b1[t];
#pragma unroll 8
        for (int k = 0; k < D; ++k) h += gs[k] * w1[k * 64 + t];
        hs[t] = fmaxf(h, 0.f);
    }
    __syncthreads();

    if (t == 0) {
        float o0 = b2[0], o1 = b2[1];
#pragma unroll 8
        for (int j = 0; j < 64; ++j) {
            o0 += hs[j] * w2[2 * j];
            o1 += hs[j] * w2[2 * j + 1];
        }
        float m = fmaxf(o0, o1);
        float e0 = expf(o0 - m), e1 = expf(o1 - m);
        float s = e0 + e1;
        out[2 * b]     = e0 / s;
        out[2 * b + 1] = e1 / s;
    }
}

// ---------------------------------------------------------------------------
extern "C" void kernel_launch(void* const* d_in, const int* in_sizes, int n_in,
                              void* d_out, int out_size) {
    const int*   x_idx   = (const int*)d_in[0];
    const int*   edge    = (const int*)d_in[1];
    const int*   batch   = (const int*)d_in[2];
    const float* emb     = (const float*)d_in[3];
    const float* conv_w1 = (const float*)d_in[4];
    const float* conv_b1 = (const float*)d_in[5];
    const float* conv_w2 = (const float*)d_in[6];
    const float* conv_b2 = (const float*)d_in[7];
    const float* mlp_w1  = (const float*)d_in[8];
    const float* mlp_b1  = (const float*)d_in[9];
    const float* mlp_w2  = (const float*)d_in[10];
    const float* mlp_b2  = (const float*)d_in[11];
    float* out = (float*)d_out;

    const int nNodes = in_sizes[0];
    const int nEdges = in_sizes[1] / 2;
    const int nVocab = in_sizes[3] / D;
    const int* src = edge;
    const int* dst = edge + nEdges;

    float *px, *py, *pembT;
    cudaGetSymbolAddress((void**)&px,    g_x);
    cudaGetSymbolAddress((void**)&py,    g_y);
    cudaGetSymbolAddress((void**)&pembT, g_embT);

    const int smem_small = 2 * TILE_B;   // 69632
    const int smem_big   = 3 * TILE_B;   // 104448
    cudaFuncSetAttribute(mlp_mma<0>, cudaFuncAttributeMaxDynamicSharedMemorySize, smem_small);
    cudaFuncSetAttribute(mlp_mma<1>, cudaFuncAttributeMaxDynamicSharedMemorySize, smem_small);
    cudaFuncSetAttribute(mlp_mma<2>, cudaFuncAttributeMaxDynamicSharedMemorySize, smem_big);

    const int nodeTiles = (nNodes + TMG - 1) / TMG;    // 32-row tiles
    const int embTiles  = (nVocab + TMG - 1) / TMG;
    const int grid1 = (nodeTiles + NGROUP - 1) / NGROUP < 148
                          ? (nodeTiles + NGROUP - 1) / NGROUP : 148;
    const int gridE = (embTiles + NGROUP - 1) / NGROUP < 148
                          ? (embTiles + NGROUP - 1) / NGROUP : 148;
    const int nb = (nNodes + SCAN_BLK - 1) / SCAN_BLK;

    // CSR build + zeros + weight prep
    zero_kernel<<<256, 256>>>();
    prep_weights<<<(6 * D * D + 255) / 256, 256>>>(conv_w1, conv_w2);
    hist_kernel<<<(nEdges + 255) / 256, 256>>>(dst, nEdges);
    scanA_kernel<<<nb, SCAN_BLK>>>(nNodes);
    scanB_kernel<<<1, NB_MAX>>>(nb);
    scanC_kernel<<<nb, SCAN_BLK>>>(nNodes);
    fill_kernel<<<(nEdges + 255) / 256, 256>>>(src, dst, nEdges);

    // embT = emb @ conv_w1[0]
    mlp_mma<0><<<gridE, NT_MLP, smem_small>>>(emb, nullptr, -1, 0, nullptr, nullptr,
                                              pembT, nullptr, nVocab, embTiles);

    // layer 0 (fused gather + aggregate): embT[x_idx] pull -> px
    mlp_mma<1><<<grid1, NT_MLP, smem_small>>>(nullptr, x_idx, -1, 3, conv_b1, conv_b2,
                                              px, nullptr, nNodes, nodeTiles);

    // layer 1: px -> py
    mlp_mma<2><<<grid1, NT_MLP, smem_big>>>(px, nullptr, 1, 4, conv_b1 + D, conv_b2 + D,
                                            py, nullptr, nNodes, nodeTiles);

    // layer 2: py -> pooled sums
    mlp_mma<2><<<grid1, NT_MLP, smem_big>>>(py, nullptr, 2, 5, conv_b1 + 2 * D,
                                            conv_b2 + 2 * D, nullptr, batch,
                                            nNodes, nodeTiles);

    // classifier + softmax
    classifier_kernel<<<N_GRAPHS, D>>>(batch, nNodes, mlp_w1, mlp_b1, mlp_w2,
                                       mlp_b2, out);
}